// round 13
// baseline (speedup 1.0000x reference)
#include <cuda_runtime.h>
#include <cuda_bf16.h>
#include <math.h>
#include <stdint.h>

#define Bsz 64
#define Dd  768
#define VOC 100000
#define KTOP 512

typedef unsigned long long u64t;

// ---------- scratch ----------
__device__ float g_x [Bsz*3072];
__device__ float g_h1[Bsz*2304];
__device__ float g_h2[Bsz*1700];
__device__ float g_h3[Bsz*1000];
__device__ float g_h4[Bsz*768];
__device__ float g_mo[Bsz*768];
__device__ uint2 g_bfh[48*8*32];               // hi bf16 B fragments [k16][n8][lane]
__device__ uint2 g_bfl[48*8*32];               // lo bf16 B fragments
__device__ float g_cluet[Bsz*768*32];          // cols 25..31 never written -> zero
__device__ float g_sims[(size_t)Bsz*VOC];
__device__ unsigned g_hist[Bsz*65536];         // zero-invariant across replays
__device__ int      g_thr[Bsz];
__device__ unsigned g_cnt[Bsz];
__device__ u64t     g_cand[Bsz*4096];
__device__ int   g_topidx[Bsz*KTOP];
__device__ float g_tot[Bsz*KTOP];
__device__ int   g_flags[Bsz*KTOP];
__device__ int   g_search[Bsz];
__device__ float g_part[3538944];
__device__ float g_pp[Bsz*8*2*768];

__device__ __forceinline__ unsigned f2u(float f){
    unsigned u = __float_as_uint(f);
    return (u & 0x80000000u) ? ~u : (u | 0x80000000u);
}
__device__ __forceinline__ u64t ffma2(u64t a, u64t b, u64t c){
    u64t d;
    asm("fma.rn.f32x2 %0, %1, %2, %3;" : "=l"(d) : "l"(a), "l"(b), "l"(c));
    return d;
}
__device__ __forceinline__ float u2lo(u64t v){ return __uint_as_float((unsigned)v); }
__device__ __forceinline__ float u2hi(u64t v){ return __uint_as_float((unsigned)(v>>32)); }

__device__ __forceinline__ void fsplit2(float2 f, unsigned &hi, unsigned &lo){
    unsigned h;
    asm("cvt.rn.bf16x2.f32 %0, %1, %2;" : "=r"(h) : "f"(f.y), "f"(f.x));
    float h0=__uint_as_float(h<<16);
    float h1=__uint_as_float(h&0xffff0000u);
    float l0=f.x-h0, l1=f.y-h1;
    asm("cvt.rn.bf16x2.f32 %0, %1, %2;" : "=r"(lo) : "f"(l1), "f"(l0));
    hi=h;
}

#define MMA_BF16(D,A0,A1,A2,A3,B0,B1) \
  asm volatile("mma.sync.aligned.m16n8k16.row.col.f32.bf16.bf16.f32 " \
    "{%0,%1,%2,%3},{%4,%5,%6,%7},{%8,%9},{%0,%1,%2,%3};" \
    : "+f"(D[0]),"+f"(D[1]),"+f"(D[2]),"+f"(D[3]) \
    : "r"(A0),"r"(A1),"r"(A2),"r"(A3),"r"(B0),"r"(B1))

#define CP16(dst,src) asm volatile("cp.async.cg.shared.global [%0], [%1], 16;" :: "r"(dst), "l"(src))

// ---------- stage 1 fused: pool-concat (g<4) + clue-norm (g>=4) ----------
__global__ void prep_k(const float* __restrict__ pos, const float* __restrict__ neg,
                       const float* __restrict__ neut, const float* __restrict__ assas){
    int b=blockIdx.y, g=blockIdx.x, t=threadIdx.x;
    __shared__ float red[256];
    if(g<4){
        const float* src; int n, xoff;
        if(g==0){src=neg +(size_t)b*8*Dd; n=8; xoff=0;}
        else if(g==1){src=assas+(size_t)b*Dd; n=1; xoff=Dd;}
        else if(g==2){src=neut+(size_t)b*7*Dd; n=7; xoff=2*Dd;}
        else {src=pos +(size_t)b*9*Dd; n=9; xoff=3*Dd;}
        float m[3];
#pragma unroll
        for(int i=0;i<3;i++){int d=t+i*256; float s=0.f;
            for(int j=0;j<n;j++) s+=src[(size_t)j*Dd+d]; m[i]=s/(float)n;}
        if(g==1){
#pragma unroll
            for(int i=0;i<3;i++) g_x[b*3072+xoff+t+i*256]=m[i];
            return;
        }
        red[t]=m[0]*m[0]+m[1]*m[1]+m[2]*m[2]; __syncthreads();
        for(int s=128;s>0;s>>=1){ if(t<s) red[t]+=red[t+s]; __syncthreads(); }
        float inv=1.f/fmaxf(sqrtf(red[0]),1e-12f);
#pragma unroll
        for(int i=0;i<3;i++) g_x[b*3072+xoff+t+i*256]=m[i]*inv;
    } else {
        int c=g-4;
        const float* src;
        if(c<9)       src=pos +((size_t)b*9+c)*Dd;
        else if(c<17) src=neg +((size_t)b*8+(c-9))*Dd;
        else if(c<24) src=neut+((size_t)b*7+(c-17))*Dd;
        else          src=assas+(size_t)b*Dd;
        float m[3]; float loc=0.f;
#pragma unroll
        for(int i=0;i<3;i++){ m[i]=src[t+i*256]; loc+=m[i]*m[i]; }
        red[t]=loc; __syncthreads();
        for(int s=128;s>0;s>>=1){ if(t<s) red[t]+=red[t+s]; __syncthreads(); }
        float inv=1.f/fmaxf(sqrtf(red[0]),1e-12f);
#pragma unroll
        for(int i=0;i<3;i++) g_cluet[((size_t)b*768+t+i*256)*32+c]=m[i]*inv;
    }
}

// ---------- MLP GEMM: exact fp32 FFMA2, 256 threads, tile 128 neurons x 64 rows ----------
__global__ void __launch_bounds__(256) gemmT_k(const float* __restrict__ X, const float* __restrict__ W,
        float* __restrict__ part, int Kdim, int Ndim, int kchunk){
    __shared__ float ws[16][132];
    __shared__ float msd[16][132];
    int tid=threadIdx.x;
    int n0=blockIdx.x*128;
    int kbeg=blockIdx.y*kchunk, kend=min(Kdim,kbeg+kchunk);
    int rg=tid&31, cg=tid>>5;
    u64t acc2[2][8];
#pragma unroll
    for(int i=0;i<2;i++)
#pragma unroll
        for(int j=0;j<8;j++) acc2[i][j]=0ull;

    float4 wr[2], xr;
#pragma unroll
    for(int i=0;i<2;i++){
        int q=tid+i*256; int kr=q>>5, c4=(q&31)*4;
        int k=kbeg+kr, n=n0+c4;
        float4 v=make_float4(0,0,0,0);
        if(k<kend && n<Ndim) v=*(const float4*)(W+(size_t)k*Ndim+n);
        wr[i]=v;
    }
    {
        int r=tid>>2, c4=(tid&3)*4;
        int k=kbeg+c4;
        xr=make_float4(0,0,0,0);
        if(k<kend) xr=*(const float4*)(X+(size_t)r*Kdim+k);
    }
    for(int k0=kbeg;k0<kend;k0+=16){
#pragma unroll
        for(int i=0;i<2;i++){
            int q=tid+i*256; int kr=q>>5, c4=(q&31)*4;
            *(float4*)&ws[kr][c4]=wr[i];
        }
        {
            int r=tid>>2, c4=(tid&3)*4;
            float vv[4]={xr.x,xr.y,xr.z,xr.w};
#pragma unroll
            for(int j=0;j<4;j++)
                *(float2*)&msd[c4+j][2*r]=make_float2(vv[j],vv[j]);
        }
        __syncthreads();
        int kn=k0+16;
        if(kn<kend){
#pragma unroll
            for(int i=0;i<2;i++){
                int q=tid+i*256; int kr=q>>5, c4=(q&31)*4;
                int k=kn+kr, n=n0+c4;
                float4 v=make_float4(0,0,0,0);
                if(k<kend && n<Ndim) v=*(const float4*)(W+(size_t)k*Ndim+n);
                wr[i]=v;
            }
            {
                int r=tid>>2, c4=(tid&3)*4;
                int k=kn+c4;
                xr=make_float4(0,0,0,0);
                if(k<kend) xr=*(const float4*)(X+(size_t)r*Kdim+k);
            }
        }
#pragma unroll
        for(int kk=0;kk<16;kk++){
            const u64t* ap=(const u64t*)&ws[kk][rg*4];
            u64t a0=ap[0], a1=ap[1];
            const u64t* bp=(const u64t*)&msd[kk][cg*16];
#pragma unroll
            for(int j=0;j<8;j++){
                u64t bv=bp[j];
                acc2[0][j]=ffma2(a0,bv,acc2[0][j]);
                acc2[1][j]=ffma2(a1,bv,acc2[1][j]);
            }
        }
        __syncthreads();
    }
    float* dst=part+(size_t)blockIdx.y*Bsz*Ndim;
#pragma unroll
    for(int i=0;i<2;i++){
        int n=n0+rg*4+2*i;
#pragma unroll
        for(int j=0;j<8;j++){
            int row=cg*8+j;
            if(n<Ndim)   dst[(size_t)row*Ndim+n]  =u2lo(acc2[i][j]);
            if(n+1<Ndim) dst[(size_t)row*Ndim+n+1]=u2hi(acc2[i][j]);
        }
    }
}

__global__ void combine_act_k(const float* __restrict__ part, const float* __restrict__ bias,
                              float* __restrict__ Y, int Ndim, int S, int act){
    int idx=blockIdx.x*blockDim.x+threadIdx.x;
    int total=Bsz*Ndim;
    if(idx>=total) return;
    int c=idx%Ndim;
    float s=bias[c];
    for(int sp=0;sp<S;sp++) s+=part[(size_t)sp*total+idx];
    Y[idx]=act?tanhf(s):s;
}

__global__ void norm_mo_k(float* __restrict__ out){
    int b=blockIdx.x, t=threadIdx.x;
    __shared__ float red[256];
    float m[3]; float loc=0.f;
#pragma unroll
    for(int i=0;i<3;i++){ m[i]=g_h4[b*768+t+i*256]; loc+=m[i]*m[i]; }
    red[t]=loc; __syncthreads();
    for(int s=128;s>0;s>>=1){ if(t<s) red[t]+=red[t+s]; __syncthreads(); }
    float inv=1.f/fmaxf(sqrtf(red[0]),1e-12f);
#pragma unroll
    for(int i=0;i<3;i++){
        float v=m[i]*inv;
        int k=t+i*256;
        g_mo[b*768+k]=v;
        out[b*768+k]=v;
    }
}

// ---------- B fragments: model_out split to bf16 hi/lo in mma layout ----------
__global__ void bfrag_k(){
    int k16=blockIdx.x, nb=blockIdx.y, lane=threadIdx.x;
    int g=lane>>2, tq=lane&3;
    int n=nb*8+g;
    int k0=k16*16+tq*2;
    const float* B=g_mo+(size_t)n*768;
    float2 v0=make_float2(B[k0],B[k0+1]);
    float2 v1=make_float2(B[k0+8],B[k0+9]);
    unsigned h0,l0,h1,l1;
    fsplit2(v0,h0,l0); fsplit2(v1,h1,l1);
    g_bfh[(k16*8+nb)*32+lane]=make_uint2(h0,h1);
    g_bfl[(k16*8+nb)*32+lane]=make_uint2(l0,l1);
}

// ---------- sims: split-bf16 mma, cp.async double-buffer, 512 thr / 1 m-tile per warp ----------
#define RSTR 20
__global__ void __launch_bounds__(512) sims_mma_k(const float* __restrict__ vocab){
    __shared__ float sbuf[2][256*RSTR];
    int tid=threadIdx.x, w=tid>>5, lane=tid&31;
    int g=lane>>2, tq=lane&3;
    int base=blockIdx.x*256 + w*16;
    int r0=base+g, r1=base+8+g;
    bool ok0=r0<VOC, ok1=r1<VOC;

    // cp.async producer: 1024 chunks of 16B over 512 threads (2 each)
    const float* src[2];
    unsigned doff[2];
#pragma unroll
    for(int i=0;i<2;i++){
        int q=i*512+tid;
        int rowl=q>>2, seg=q&3;
        int rowg=blockIdx.x*256+rowl; if(rowg>=VOC) rowg=VOC-1;
        src[i]=vocab+(size_t)rowg*768+seg*4;
        doff[i]=(unsigned)((rowl*RSTR+seg*4)*4);
    }
    unsigned sb0=(unsigned)__cvta_generic_to_shared(&sbuf[0][0]);
    unsigned sb1=(unsigned)__cvta_generic_to_shared(&sbuf[1][0]);

#pragma unroll
    for(int i=0;i<2;i++) CP16(sb0+doff[i], src[i]);
    asm volatile("cp.async.commit_group;" ::: "memory");

    float d[8][4];
#pragma unroll
    for(int i=0;i<8;i++)
#pragma unroll
        for(int j=0;j<4;j++) d[i][j]=0.f;
    float sq0=0.f, sq1=0.f;

    int rl0=w*16+g, rl1=w*16+8+g;

    for(int k16=0;k16<48;k16++){
        unsigned sbn=(k16&1)?sb0:sb1;
        if(k16<47){
#pragma unroll
            for(int i=0;i<2;i++) CP16(sbn+doff[i], src[i]+(k16+1)*16);
            asm volatile("cp.async.commit_group;" ::: "memory");
            asm volatile("cp.async.wait_group 1;" ::: "memory");
        } else {
            asm volatile("cp.async.wait_group 0;" ::: "memory");
        }
        __syncthreads();
        const float* bp=(k16&1)?sbuf[1]:sbuf[0];
        float2 f0a=*(const float2*)(bp+rl0*RSTR+tq*2);
        float2 f0b=*(const float2*)(bp+rl0*RSTR+tq*2+8);
        float2 f1a=*(const float2*)(bp+rl1*RSTR+tq*2);
        float2 f1b=*(const float2*)(bp+rl1*RSTR+tq*2+8);
        sq0+=f0a.x*f0a.x+f0a.y*f0a.y+f0b.x*f0b.x+f0b.y*f0b.y;
        sq1+=f1a.x*f1a.x+f1a.y*f1a.y+f1b.x*f1b.x+f1b.y*f1b.y;
        unsigned ah0a,al0a, ah0b,al0b, ah1a,al1a, ah1b,al1b;
        fsplit2(f0a,ah0a,al0a); fsplit2(f0b,ah0b,al0b);
        fsplit2(f1a,ah1a,al1a); fsplit2(f1b,ah1b,al1b);
        const uint2* bhp=g_bfh+(size_t)k16*256+lane;
        const uint2* blp=g_bfl+(size_t)k16*256+lane;
#pragma unroll
        for(int nb=0;nb<8;nb++){
            uint2 bh=bhp[nb*32];
            uint2 bl=blp[nb*32];
            MMA_BF16(d[nb],ah0a,ah1a,ah0b,ah1b,bh.x,bh.y);
            MMA_BF16(d[nb],al0a,al1a,al0b,al1b,bh.x,bh.y);
            MMA_BF16(d[nb],ah0a,ah1a,ah0b,ah1b,bl.x,bl.y);
        }
        __syncthreads();
    }
    sq0+=__shfl_xor_sync(0xffffffff,sq0,1); sq0+=__shfl_xor_sync(0xffffffff,sq0,2);
    sq1+=__shfl_xor_sync(0xffffffff,sq1,1); sq1+=__shfl_xor_sync(0xffffffff,sq1,2);
    float ri0=1.f/fmaxf(sqrtf(sq0),1e-12f);
    float ri1=1.f/fmaxf(sqrtf(sq1),1e-12f);
#pragma unroll
    for(int nb=0;nb<8;nb++){
        int n0=nb*8+tq*2;
        if(ok0){
            float s0=d[nb][0]*ri0, s1=d[nb][1]*ri0;
            g_sims[(size_t)n0*VOC+r0]=s0;
            g_sims[(size_t)(n0+1)*VOC+r0]=s1;
            atomicAdd(&g_hist[(size_t)n0*65536+(f2u(s0)>>16)],1u);
            atomicAdd(&g_hist[(size_t)(n0+1)*65536+(f2u(s1)>>16)],1u);
        }
        if(ok1){
            float s2=d[nb][2]*ri1, s3=d[nb][3]*ri1;
            g_sims[(size_t)n0*VOC+r1]=s2;
            g_sims[(size_t)(n0+1)*VOC+r1]=s3;
            atomicAdd(&g_hist[(size_t)n0*65536+(f2u(s2)>>16)],1u);
            atomicAdd(&g_hist[(size_t)(n0+1)*65536+(f2u(s3)>>16)],1u);
        }
    }
}

// ---------- top-512 ----------
__global__ void sel_k(){
    int b=blockIdx.x, t=threadIdx.x;  // 1024
    __shared__ unsigned ssum[1024];
    unsigned* h=g_hist+(size_t)b*65536;
    int base=t*64;
    unsigned s=0;
    for(int i=0;i<64;i++) s+=h[base+i];
    ssum[t]=s; __syncthreads();
    unsigned above=0;
    for(int j=t+1;j<1024;j++) above+=ssum[j];
    if(above<512u && above+s>=512u){
        unsigned run=above;
        for(int i=63;i>=0;i--){
            unsigned hv=h[base+i];
            if(run+hv>=512u){ g_thr[b]=base+i; break; }
            run+=hv;
        }
    }
    __syncthreads();
#pragma unroll
    for(int i=0;i<64;i++) h[i*1024+t]=0u;   // coalesced re-zero (zero-invariant)
    if(t==0) g_cnt[b]=0u;
}
__global__ void collect_k(){
    int b=blockIdx.y, t=threadIdx.x;
    int start=blockIdx.x*12500, end=start+12500;
    unsigned binb=(unsigned)g_thr[b];
    const float* srow=g_sims+(size_t)b*VOC;
    for(int v=start+t;v<end;v+=512){
        unsigned u=f2u(srow[v]);
        if((u>>16)>=binb){
            unsigned pos=atomicAdd(&g_cnt[b],1u);
            if(pos<4096u) g_cand[(size_t)b*4096+pos]=((u64t)(~u)<<32)|(unsigned)v;
        }
    }
}
__global__ void final_sel_k(){
    int b=blockIdx.x, t=threadIdx.x;  // 512
    __shared__ u64t cand[4096];
    __shared__ u64t outk[512];
    int m=min(g_cnt[b],4096u);
    for(int i=t;i<m;i+=512) cand[i]=g_cand[(size_t)b*4096+i];
    __syncthreads();
    for(int i=t;i<m;i+=512){
        u64t key=cand[i]; int rank=0;
        for(int j=0;j<m;j++) rank+=(cand[j]<key);
        if(rank<512) outk[rank]=key;
    }
    __syncthreads();
    g_topidx[b*512+t]=(int)(outk[t]&0xffffffffu);
}

// ---------- gathered clue GEMM (FFMA2) + primary/secondary ----------
__global__ void __launch_bounds__(128) combined_k(const float* __restrict__ vocab){
    __shared__ float wsd[16][132];
    __shared__ float cs[16][32];
    __shared__ int sidx[64];
    __shared__ float outc[64][32];
    int b=blockIdx.y, w0=blockIdx.x*64, tid=threadIdx.x; // 128
    if(tid<64) sidx[tid]=g_topidx[b*512+w0+tid];
    __syncthreads();
    int c2=tid&15, g=tid>>4;
    u64t acc2[8];
#pragma unroll
    for(int i=0;i<8;i++) acc2[i]=0ull;
    for(int k0=0;k0<768;k0+=16){
#pragma unroll
        for(int i=0;i<2;i++){
            int q=tid+i*128, r=q>>2, c4=(q&3)*4;
            float4 v=*(const float4*)(vocab+(size_t)sidx[r]*768+k0+c4);
            float vv[4]={v.x,v.y,v.z,v.w};
#pragma unroll
            for(int j=0;j<4;j++)
                *(float2*)&wsd[c4+j][2*r]=make_float2(vv[j],vv[j]);
        }
        {
            int kk=tid>>3, cc4=(tid&7)*4;
            *(float4*)&cs[kk][cc4]=*(const float4*)(g_cluet+((size_t)b*768+k0+kk)*32+cc4);
        }
        __syncthreads();
#pragma unroll
        for(int kk=0;kk<16;kk++){
            u64t cv=*(const u64t*)&cs[kk][c2*2];
            const u64t* bp=(const u64t*)&wsd[kk][g*16];
#pragma unroll
            for(int j=0;j<8;j++)
                acc2[j]=ffma2(bp[j],cv,acc2[j]);
        }
        __syncthreads();
    }
#pragma unroll
    for(int j=0;j<8;j++){
        outc[g*8+j][2*c2]  =u2lo(acc2[j]);
        outc[g*8+j][2*c2+1]=u2hi(acc2[j]);
    }
    __syncthreads();
    if(tid<64){
        float* row=outc[tid];
        float mbest=-1e30f; int jbest=9;
        for(int j=9;j<25;j++){ float v=row[j]; if(v>mbest){mbest=v; jbest=j;} }
        int primary=0;
        for(int p=0;p<9;p++) primary+=(row[p]>=mbest);
        float sec=(jbest<17)?0.f:((jbest<24)?1.f:-10.f);
        g_tot[b*512+w0+tid]=(float)primary+sec;
    }
}

// ---------- rank ----------
__global__ void rank_k(){
    int b=blockIdx.x, t=threadIdx.x; // 512
    __shared__ float tv[512];
    tv[t]=g_tot[b*512+t]; __syncthreads();
    float mv=tv[t]; int gt=0, lt=0, eqb=0;
    for(int j=0;j<512;j++){
        float o=tv[j];
        gt+=(o>mv); lt+=(o<mv); eqb+=((o==mv)&&(j<t));
    }
    int rmax=gt+eqb, rmin=lt+eqb;
    g_flags[b*512+t]=((rmax<256)?1:0)|((rmin<256)?2:0);
    if(rmax==0) g_search[b]=g_topidx[b*512+t];
}

// ---------- final pooled outputs ----------
__global__ void final_acc_k(const float* __restrict__ vocab){
    int b=blockIdx.y, c=blockIdx.x, t=threadIdx.x; // 256
    const int* ti=g_topidx+b*512+c*64;
    const int* fl=g_flags+b*512+c*64;
    float amax[3]={0,0,0}, amin[3]={0,0,0};
    for(int w=0;w<64;w++){
        int f=fl[w];
        if(f){
            const float* row=vocab+(size_t)ti[w]*768;
#pragma unroll
            for(int i=0;i<3;i++){
                float v=row[t+i*256];
                if(f&1) amax[i]+=v;
                if(f&2) amin[i]+=v;
            }
        }
    }
    float* pp=g_pp+(size_t)(b*8+c)*2*768;
#pragma unroll
    for(int i=0;i<3;i++){
        pp[t+i*256]=amax[i];
        pp[768+t+i*256]=amin[i];
    }
}
__global__ void final_red_k(const float* __restrict__ vocab, float* __restrict__ out){
    int b=blockIdx.x, t=threadIdx.x; // 256
    __shared__ float red[256];
    float amax[3]={0,0,0}, amin[3]={0,0,0};
    for(int c=0;c<8;c++){
        const float* pp=g_pp+(size_t)(b*8+c)*2*768;
#pragma unroll
        for(int i=0;i<3;i++){
            amax[i]+=pp[t+i*256];
            amin[i]+=pp[768+t+i*256];
        }
    }
    float loc=0.f;
#pragma unroll
    for(int i=0;i<3;i++){ amax[i]*=(1.f/256.f); loc+=amax[i]*amax[i]; }
    red[t]=loc; __syncthreads();
    for(int s=128;s>0;s>>=1){ if(t<s) red[t]+=red[t+s]; __syncthreads(); }
    float inv=1.f/fmaxf(sqrtf(red[0]),1e-12f);
#pragma unroll
    for(int i=0;i<3;i++) out[2*49152+b*768+t+i*256]=amax[i]*inv;
    __syncthreads();
    loc=0.f;
#pragma unroll
    for(int i=0;i<3;i++){ amin[i]*=(1.f/256.f); loc+=amin[i]*amin[i]; }
    red[t]=loc; __syncthreads();
    for(int s=128;s>0;s>>=1){ if(t<s) red[t]+=red[t+s]; __syncthreads(); }
    inv=1.f/fmaxf(sqrtf(red[0]),1e-12f);
#pragma unroll
    for(int i=0;i<3;i++) out[3*49152+b*768+t+i*256]=amin[i]*inv;
    int sw=g_search[b];
#pragma unroll
    for(int i=0;i<3;i++) out[49152+b*768+t+i*256]=vocab[(size_t)sw*768+t+i*256];
}

extern "C" void kernel_launch(void* const* d_in, const int* in_sizes, int n_in,
                              void* d_out, int out_size){
    const float* pos  =(const float*)d_in[0];
    const float* neg  =(const float*)d_in[1];
    const float* neut =(const float*)d_in[2];
    const float* assas=(const float*)d_in[3];
    const float* vocab=(const float*)d_in[4];
    const float* W1=(const float*)d_in[5];  const float* b1=(const float*)d_in[6];
    const float* W2=(const float*)d_in[7];  const float* b2=(const float*)d_in[8];
    const float* W3=(const float*)d_in[9];  const float* b3=(const float*)d_in[10];
    const float* W4=(const float*)d_in[11]; const float* b4=(const float*)d_in[12];
    float* out=(float*)d_out;

    float *gx, *gh1, *gh2, *gh3, *gh4, *gpart;
    cudaGetSymbolAddress((void**)&gx,   g_x);
    cudaGetSymbolAddress((void**)&gh1,  g_h1);
    cudaGetSymbolAddress((void**)&gh2,  g_h2);
    cudaGetSymbolAddress((void**)&gh3,  g_h3);
    cudaGetSymbolAddress((void**)&gh4,  g_h4);
    cudaGetSymbolAddress((void**)&gpart,g_part);

    prep_k<<<dim3(29,64),256>>>(pos,neg,neut,assas);

    // exact fp32 MLP
    gemmT_k<<<dim3(18,24),256>>>(gx,W1,gpart,3072,2304,128);
    combine_act_k<<<(64*2304+255)/256,256>>>(gpart,b1,gh1,2304,24,1);
    gemmT_k<<<dim3(14,29),256>>>(gh1,W2,gpart,2304,1700,80);
    combine_act_k<<<(64*1700+255)/256,256>>>(gpart,b2,gh2,1700,29,1);
    gemmT_k<<<dim3(8,36),256>>>(gh2,W3,gpart,1700,1000,48);
    combine_act_k<<<(64*1000+255)/256,256>>>(gpart,b3,gh3,1000,36,1);
    gemmT_k<<<dim3(6,32),256>>>(gh3,W4,gpart,1000,768,32);
    combine_act_k<<<(64*768+255)/256,256>>>(gpart,b4,gh4,768,32,0);

    norm_mo_k<<<64,256>>>(out);
    bfrag_k<<<dim3(48,8),32>>>();
    sims_mma_k<<<(VOC+255)/256,512>>>(vocab);

    sel_k<<<64,1024>>>();
    collect_k<<<dim3(8,64),512>>>();
    final_sel_k<<<64,512>>>();

    combined_k<<<dim3(8,64),128>>>(vocab);
    rank_k<<<64,512>>>();
    final_acc_k<<<dim3(8,64),256>>>(vocab);
    final_red_k<<<64,256>>>(vocab,out);
}

// round 14
// speedup vs baseline: 1.0403x; 1.0403x over previous
#include <cuda_runtime.h>
#include <cuda_bf16.h>
#include <math.h>
#include <stdint.h>

#define Bsz 64
#define Dd  768
#define VOC 100000
#define KTOP 512

typedef unsigned long long u64t;

// ---------- scratch ----------
__device__ float g_x [Bsz*3072];
__device__ float g_h1[Bsz*2304];
__device__ float g_h2[Bsz*1700];
__device__ float g_h3[Bsz*1000];
__device__ float g_h4[Bsz*768];
__device__ float g_mo[Bsz*768];
__device__ uint4 g_bfh4[48*32*4];              // hi bf16 B fragments [k16][lane][nb/2]
__device__ uint4 g_bfl4[48*32*4];              // lo bf16 B fragments
__device__ float g_cluet[Bsz*768*32];          // cols 25..31 never written -> zero
__device__ float g_sims[(size_t)Bsz*VOC];
__device__ unsigned g_hist[Bsz*65536];         // zero-invariant across replays
__device__ int      g_thr[Bsz];
__device__ unsigned g_cnt[Bsz];
__device__ u64t     g_cand[Bsz*4096];
__device__ int   g_topidx[Bsz*KTOP];
__device__ float g_tot[Bsz*KTOP];
__device__ int   g_flags[Bsz*KTOP];
__device__ int   g_search[Bsz];
__device__ float g_part[3538944];
__device__ float g_pp[Bsz*8*2*768];

__device__ __forceinline__ unsigned f2u(float f){
    unsigned u = __float_as_uint(f);
    return (u & 0x80000000u) ? ~u : (u | 0x80000000u);
}
__device__ __forceinline__ u64t ffma2(u64t a, u64t b, u64t c){
    u64t d;
    asm("fma.rn.f32x2 %0, %1, %2, %3;" : "=l"(d) : "l"(a), "l"(b), "l"(c));
    return d;
}
__device__ __forceinline__ float u2lo(u64t v){ return __uint_as_float((unsigned)v); }
__device__ __forceinline__ float u2hi(u64t v){ return __uint_as_float((unsigned)(v>>32)); }

__device__ __forceinline__ void fsplit2(float2 f, unsigned &hi, unsigned &lo){
    unsigned h;
    asm("cvt.rn.bf16x2.f32 %0, %1, %2;" : "=r"(h) : "f"(f.y), "f"(f.x));
    float h0=__uint_as_float(h<<16);
    float h1=__uint_as_float(h&0xffff0000u);
    float l0=f.x-h0, l1=f.y-h1;
    asm("cvt.rn.bf16x2.f32 %0, %1, %2;" : "=r"(lo) : "f"(l1), "f"(l0));
    hi=h;
}

#define MMA_BF16(D,A0,A1,A2,A3,B0,B1) \
  asm volatile("mma.sync.aligned.m16n8k16.row.col.f32.bf16.bf16.f32 " \
    "{%0,%1,%2,%3},{%4,%5,%6,%7},{%8,%9},{%0,%1,%2,%3};" \
    : "+f"(D[0]),"+f"(D[1]),"+f"(D[2]),"+f"(D[3]) \
    : "r"(A0),"r"(A1),"r"(A2),"r"(A3),"r"(B0),"r"(B1))

#define CP16(dst,src) asm volatile("cp.async.cg.shared.global [%0], [%1], 16;" :: "r"(dst), "l"(src))

// ---------- stage 1 fused: pool-concat (g<4) + clue-norm (g>=4) ----------
__global__ void prep_k(const float* __restrict__ pos, const float* __restrict__ neg,
                       const float* __restrict__ neut, const float* __restrict__ assas){
    int b=blockIdx.y, g=blockIdx.x, t=threadIdx.x;
    __shared__ float red[256];
    if(g<4){
        const float* src; int n, xoff;
        if(g==0){src=neg +(size_t)b*8*Dd; n=8; xoff=0;}
        else if(g==1){src=assas+(size_t)b*Dd; n=1; xoff=Dd;}
        else if(g==2){src=neut+(size_t)b*7*Dd; n=7; xoff=2*Dd;}
        else {src=pos +(size_t)b*9*Dd; n=9; xoff=3*Dd;}
        float m[3];
#pragma unroll
        for(int i=0;i<3;i++){int d=t+i*256; float s=0.f;
            for(int j=0;j<n;j++) s+=src[(size_t)j*Dd+d]; m[i]=s/(float)n;}
        if(g==1){
#pragma unroll
            for(int i=0;i<3;i++) g_x[b*3072+xoff+t+i*256]=m[i];
            return;
        }
        red[t]=m[0]*m[0]+m[1]*m[1]+m[2]*m[2]; __syncthreads();
        for(int s=128;s>0;s>>=1){ if(t<s) red[t]+=red[t+s]; __syncthreads(); }
        float inv=1.f/fmaxf(sqrtf(red[0]),1e-12f);
#pragma unroll
        for(int i=0;i<3;i++) g_x[b*3072+xoff+t+i*256]=m[i]*inv;
    } else {
        int c=g-4;
        const float* src;
        if(c<9)       src=pos +((size_t)b*9+c)*Dd;
        else if(c<17) src=neg +((size_t)b*8+(c-9))*Dd;
        else if(c<24) src=neut+((size_t)b*7+(c-17))*Dd;
        else          src=assas+(size_t)b*Dd;
        float m[3]; float loc=0.f;
#pragma unroll
        for(int i=0;i<3;i++){ m[i]=src[t+i*256]; loc+=m[i]*m[i]; }
        red[t]=loc; __syncthreads();
        for(int s=128;s>0;s>>=1){ if(t<s) red[t]+=red[t+s]; __syncthreads(); }
        float inv=1.f/fmaxf(sqrtf(red[0]),1e-12f);
#pragma unroll
        for(int i=0;i<3;i++) g_cluet[((size_t)b*768+t+i*256)*32+c]=m[i]*inv;
    }
}

// ---------- MLP GEMM: exact fp32 FFMA2, 256 threads, tile 128 neurons x 64 rows ----------
__global__ void __launch_bounds__(256) gemmT_k(const float* __restrict__ X, const float* __restrict__ W,
        float* __restrict__ part, int Kdim, int Ndim, int kchunk){
    __shared__ float ws[16][132];
    __shared__ float msd[16][132];
    int tid=threadIdx.x;
    int n0=blockIdx.x*128;
    int kbeg=blockIdx.y*kchunk, kend=min(Kdim,kbeg+kchunk);
    int rg=tid&31, cg=tid>>5;
    u64t acc2[2][8];
#pragma unroll
    for(int i=0;i<2;i++)
#pragma unroll
        for(int j=0;j<8;j++) acc2[i][j]=0ull;

    float4 wr[2], xr;
#pragma unroll
    for(int i=0;i<2;i++){
        int q=tid+i*256; int kr=q>>5, c4=(q&31)*4;
        int k=kbeg+kr, n=n0+c4;
        float4 v=make_float4(0,0,0,0);
        if(k<kend && n<Ndim) v=*(const float4*)(W+(size_t)k*Ndim+n);
        wr[i]=v;
    }
    {
        int r=tid>>2, c4=(tid&3)*4;
        int k=kbeg+c4;
        xr=make_float4(0,0,0,0);
        if(k<kend) xr=*(const float4*)(X+(size_t)r*Kdim+k);
    }
    for(int k0=kbeg;k0<kend;k0+=16){
#pragma unroll
        for(int i=0;i<2;i++){
            int q=tid+i*256; int kr=q>>5, c4=(q&31)*4;
            *(float4*)&ws[kr][c4]=wr[i];
        }
        {
            int r=tid>>2, c4=(tid&3)*4;
            float vv[4]={xr.x,xr.y,xr.z,xr.w};
#pragma unroll
            for(int j=0;j<4;j++)
                *(float2*)&msd[c4+j][2*r]=make_float2(vv[j],vv[j]);
        }
        __syncthreads();
        int kn=k0+16;
        if(kn<kend){
#pragma unroll
            for(int i=0;i<2;i++){
                int q=tid+i*256; int kr=q>>5, c4=(q&31)*4;
                int k=kn+kr, n=n0+c4;
                float4 v=make_float4(0,0,0,0);
                if(k<kend && n<Ndim) v=*(const float4*)(W+(size_t)k*Ndim+n);
                wr[i]=v;
            }
            {
                int r=tid>>2, c4=(tid&3)*4;
                int k=kn+c4;
                xr=make_float4(0,0,0,0);
                if(k<kend) xr=*(const float4*)(X+(size_t)r*Kdim+k);
            }
        }
#pragma unroll
        for(int kk=0;kk<16;kk++){
            const u64t* ap=(const u64t*)&ws[kk][rg*4];
            u64t a0=ap[0], a1=ap[1];
            const u64t* bp=(const u64t*)&msd[kk][cg*16];
#pragma unroll
            for(int j=0;j<8;j++){
                u64t bv=bp[j];
                acc2[0][j]=ffma2(a0,bv,acc2[0][j]);
                acc2[1][j]=ffma2(a1,bv,acc2[1][j]);
            }
        }
        __syncthreads();
    }
    float* dst=part+(size_t)blockIdx.y*Bsz*Ndim;
#pragma unroll
    for(int i=0;i<2;i++){
        int n=n0+rg*4+2*i;
#pragma unroll
        for(int j=0;j<8;j++){
            int row=cg*8+j;
            if(n<Ndim)   dst[(size_t)row*Ndim+n]  =u2lo(acc2[i][j]);
            if(n+1<Ndim) dst[(size_t)row*Ndim+n+1]=u2hi(acc2[i][j]);
        }
    }
}

__global__ void combine_act_k(const float* __restrict__ part, const float* __restrict__ bias,
                              float* __restrict__ Y, int Ndim, int S, int act){
    int idx=blockIdx.x*blockDim.x+threadIdx.x;
    int total=Bsz*Ndim;
    if(idx>=total) return;
    int c=idx%Ndim;
    float s=bias[c];
    for(int sp=0;sp<S;sp++) s+=part[(size_t)sp*total+idx];
    Y[idx]=act?tanhf(s):s;
}

__global__ void norm_mo_k(float* __restrict__ out){
    int b=blockIdx.x, t=threadIdx.x;
    __shared__ float red[256];
    float m[3]; float loc=0.f;
#pragma unroll
    for(int i=0;i<3;i++){ m[i]=g_h4[b*768+t+i*256]; loc+=m[i]*m[i]; }
    red[t]=loc; __syncthreads();
    for(int s=128;s>0;s>>=1){ if(t<s) red[t]+=red[t+s]; __syncthreads(); }
    float inv=1.f/fmaxf(sqrtf(red[0]),1e-12f);
#pragma unroll
    for(int i=0;i<3;i++){
        float v=m[i]*inv;
        int k=t+i*256;
        g_mo[b*768+k]=v;
        out[b*768+k]=v;
    }
}

// ---------- B fragments: model_out split to bf16 hi/lo, [k16][lane][nb] layout ----------
__global__ void bfrag_k(){
    int k16=blockIdx.x, nb=blockIdx.y, lane=threadIdx.x;
    int g=lane>>2, tq=lane&3;
    int n=nb*8+g;
    int k0=k16*16+tq*2;
    const float* B=g_mo+(size_t)n*768;
    float2 v0=make_float2(B[k0],B[k0+1]);
    float2 v1=make_float2(B[k0+8],B[k0+9]);
    unsigned h0,l0,h1,l1;
    fsplit2(v0,h0,l0); fsplit2(v1,h1,l1);
    ((uint2*)g_bfh4)[((size_t)k16*32+lane)*8+nb]=make_uint2(h0,h1);
    ((uint2*)g_bfl4)[((size_t)k16*32+lane)*8+nb]=make_uint2(l0,l1);
}

// ---------- sims: split-bf16 mma, cp.async double-buffer, LDG.128 fragments ----------
#define RSTR 20
__global__ void __launch_bounds__(256) sims_mma_k(const float* __restrict__ vocab){
    __shared__ float sbuf[2][256*RSTR];
    int tid=threadIdx.x, w=tid>>5, lane=tid&31;
    int g=lane>>2, tq=lane&3;
    int base=blockIdx.x*256 + w*32;
    int r[4]={base+g, base+8+g, base+16+g, base+24+g};
    bool ok[4];
#pragma unroll
    for(int i=0;i<4;i++) ok[i]=r[i]<VOC;

    const float* src[4];
    unsigned doff[4];
#pragma unroll
    for(int i=0;i<4;i++){
        int q=i*256+tid;
        int rowl=q>>2, seg=q&3;
        int rowg=blockIdx.x*256+rowl; if(rowg>=VOC) rowg=VOC-1;
        src[i]=vocab+(size_t)rowg*768+seg*4;
        doff[i]=(unsigned)((rowl*RSTR+seg*4)*4);
    }
    unsigned sb0=(unsigned)__cvta_generic_to_shared(&sbuf[0][0]);
    unsigned sb1=(unsigned)__cvta_generic_to_shared(&sbuf[1][0]);

#pragma unroll
    for(int i=0;i<4;i++) CP16(sb0+doff[i], src[i]);
    asm volatile("cp.async.commit_group;" ::: "memory");

    float d[2][8][4];
#pragma unroll
    for(int t=0;t<2;t++)
#pragma unroll
        for(int i=0;i<8;i++)
#pragma unroll
            for(int j=0;j<4;j++) d[t][i][j]=0.f;
    float sq[4]={0,0,0,0};

    int rl[4];
#pragma unroll
    for(int i=0;i<4;i++) rl[i]=w*32+i*8+g;

    for(int k16=0;k16<48;k16++){
        unsigned sbn=(k16&1)?sb0:sb1;
        if(k16<47){
#pragma unroll
            for(int i=0;i<4;i++) CP16(sbn+doff[i], src[i]+(k16+1)*16);
            asm volatile("cp.async.commit_group;" ::: "memory");
            asm volatile("cp.async.wait_group 1;" ::: "memory");
        } else {
            asm volatile("cp.async.wait_group 0;" ::: "memory");
        }
        __syncthreads();
        const float* bp=(k16&1)?sbuf[1]:sbuf[0];
        float2 f[4][2];
#pragma unroll
        for(int i=0;i<4;i++){
            f[i][0]=*(const float2*)(bp+rl[i]*RSTR+tq*2);
            f[i][1]=*(const float2*)(bp+rl[i]*RSTR+tq*2+8);
            sq[i]+=f[i][0].x*f[i][0].x+f[i][0].y*f[i][0].y
                  +f[i][1].x*f[i][1].x+f[i][1].y*f[i][1].y;
        }
        unsigned ah[4][2], al[4][2];
#pragma unroll
        for(int i=0;i<4;i++){
            fsplit2(f[i][0],ah[i][0],al[i][0]);
            fsplit2(f[i][1],ah[i][1],al[i][1]);
        }
        // fragments: 4+4 LDG.128, each covering two nb's
        const uint4* bhp=g_bfh4+((size_t)k16*32+lane)*4;
        const uint4* blp=g_bfl4+((size_t)k16*32+lane)*4;
#pragma unroll
        for(int p=0;p<4;p++){
            uint4 bh=bhp[p];
            uint4 bl=blp[p];
            int nb0=2*p, nb1=2*p+1;
            MMA_BF16(d[0][nb0],ah[0][0],ah[1][0],ah[0][1],ah[1][1],bh.x,bh.y);
            MMA_BF16(d[0][nb0],al[0][0],al[1][0],al[0][1],al[1][1],bh.x,bh.y);
            MMA_BF16(d[0][nb0],ah[0][0],ah[1][0],ah[0][1],ah[1][1],bl.x,bl.y);
            MMA_BF16(d[1][nb0],ah[2][0],ah[3][0],ah[2][1],ah[3][1],bh.x,bh.y);
            MMA_BF16(d[1][nb0],al[2][0],al[3][0],al[2][1],al[3][1],bh.x,bh.y);
            MMA_BF16(d[1][nb0],ah[2][0],ah[3][0],ah[2][1],ah[3][1],bl.x,bl.y);
            MMA_BF16(d[0][nb1],ah[0][0],ah[1][0],ah[0][1],ah[1][1],bh.z,bh.w);
            MMA_BF16(d[0][nb1],al[0][0],al[1][0],al[0][1],al[1][1],bh.z,bh.w);
            MMA_BF16(d[0][nb1],ah[0][0],ah[1][0],ah[0][1],ah[1][1],bl.z,bl.w);
            MMA_BF16(d[1][nb1],ah[2][0],ah[3][0],ah[2][1],ah[3][1],bh.z,bh.w);
            MMA_BF16(d[1][nb1],al[2][0],al[3][0],al[2][1],al[3][1],bh.z,bh.w);
            MMA_BF16(d[1][nb1],ah[2][0],ah[3][0],ah[2][1],ah[3][1],bl.z,bl.w);
        }
        __syncthreads();
    }
    float ri[4];
#pragma unroll
    for(int i=0;i<4;i++){
        sq[i]+=__shfl_xor_sync(0xffffffff,sq[i],1);
        sq[i]+=__shfl_xor_sync(0xffffffff,sq[i],2);
        ri[i]=1.f/fmaxf(sqrtf(sq[i]),1e-12f);
    }
#pragma unroll
    for(int t=0;t<2;t++){
#pragma unroll
        for(int nb=0;nb<8;nb++){
            int n0=nb*8+tq*2;
            if(ok[2*t]){
                float s0=d[t][nb][0]*ri[2*t], s1=d[t][nb][1]*ri[2*t];
                g_sims[(size_t)n0*VOC+r[2*t]]=s0;
                g_sims[(size_t)(n0+1)*VOC+r[2*t]]=s1;
                atomicAdd(&g_hist[(size_t)n0*65536+(f2u(s0)>>16)],1u);
                atomicAdd(&g_hist[(size_t)(n0+1)*65536+(f2u(s1)>>16)],1u);
            }
            if(ok[2*t+1]){
                float s2=d[t][nb][2]*ri[2*t+1], s3=d[t][nb][3]*ri[2*t+1];
                g_sims[(size_t)n0*VOC+r[2*t+1]]=s2;
                g_sims[(size_t)(n0+1)*VOC+r[2*t+1]]=s3;
                atomicAdd(&g_hist[(size_t)n0*65536+(f2u(s2)>>16)],1u);
                atomicAdd(&g_hist[(size_t)(n0+1)*65536+(f2u(s3)>>16)],1u);
            }
        }
    }
}

// ---------- top-512 ----------
__global__ void sel_k(){
    int b=blockIdx.x, t=threadIdx.x;  // 1024
    __shared__ unsigned ssum[1024];
    unsigned* h=g_hist+(size_t)b*65536;
    int base=t*64;
    unsigned s=0;
    for(int i=0;i<64;i++) s+=h[base+i];
    ssum[t]=s; __syncthreads();
    unsigned above=0;
    for(int j=t+1;j<1024;j++) above+=ssum[j];
    if(above<512u && above+s>=512u){
        unsigned run=above;
        for(int i=63;i>=0;i--){
            unsigned hv=h[base+i];
            if(run+hv>=512u){ g_thr[b]=base+i; break; }
            run+=hv;
        }
    }
    __syncthreads();
#pragma unroll
    for(int i=0;i<64;i++) h[i*1024+t]=0u;   // coalesced re-zero (zero-invariant)
    if(t==0) g_cnt[b]=0u;
}
__global__ void collect_k(){
    int b=blockIdx.y, t=threadIdx.x;
    int start=blockIdx.x*12500, end=start+12500;
    unsigned binb=(unsigned)g_thr[b];
    const float* srow=g_sims+(size_t)b*VOC;
    for(int v=start+t;v<end;v+=512){
        unsigned u=f2u(srow[v]);
        if((u>>16)>=binb){
            unsigned pos=atomicAdd(&g_cnt[b],1u);
            if(pos<4096u) g_cand[(size_t)b*4096+pos]=((u64t)(~u)<<32)|(unsigned)v;
        }
    }
}
__global__ void final_sel_k(){
    int b=blockIdx.x, t=threadIdx.x;  // 512
    __shared__ u64t cand[4096];
    __shared__ u64t outk[512];
    int m=min(g_cnt[b],4096u);
    for(int i=t;i<m;i+=512) cand[i]=g_cand[(size_t)b*4096+i];
    __syncthreads();
    for(int i=t;i<m;i+=512){
        u64t key=cand[i]; int rank=0;
        for(int j=0;j<m;j++) rank+=(cand[j]<key);
        if(rank<512) outk[rank]=key;
    }
    __syncthreads();
    g_topidx[b*512+t]=(int)(outk[t]&0xffffffffu);
}

// ---------- gathered clue GEMM (FFMA2) + primary/secondary ----------
__global__ void __launch_bounds__(128) combined_k(const float* __restrict__ vocab){
    __shared__ float wsd[16][132];
    __shared__ float cs[16][32];
    __shared__ int sidx[64];
    __shared__ float outc[64][32];
    int b=blockIdx.y, w0=blockIdx.x*64, tid=threadIdx.x; // 128
    if(tid<64) sidx[tid]=g_topidx[b*512+w0+tid];
    __syncthreads();
    int c2=tid&15, g=tid>>4;
    u64t acc2[8];
#pragma unroll
    for(int i=0;i<8;i++) acc2[i]=0ull;
    for(int k0=0;k0<768;k0+=16){
#pragma unroll
        for(int i=0;i<2;i++){
            int q=tid+i*128, r=q>>2, c4=(q&3)*4;
            float4 v=*(const float4*)(vocab+(size_t)sidx[r]*768+k0+c4);
            float vv[4]={v.x,v.y,v.z,v.w};
#pragma unroll
            for(int j=0;j<4;j++)
                *(float2*)&wsd[c4+j][2*r]=make_float2(vv[j],vv[j]);
        }
        {
            int kk=tid>>3, cc4=(tid&7)*4;
            *(float4*)&cs[kk][cc4]=*(const float4*)(g_cluet+((size_t)b*768+k0+kk)*32+cc4);
        }
        __syncthreads();
#pragma unroll
        for(int kk=0;kk<16;kk++){
            u64t cv=*(const u64t*)&cs[kk][c2*2];
            const u64t* bp=(const u64t*)&wsd[kk][g*16];
#pragma unroll
            for(int j=0;j<8;j++)
                acc2[j]=ffma2(bp[j],cv,acc2[j]);
        }
        __syncthreads();
    }
#pragma unroll
    for(int j=0;j<8;j++){
        outc[g*8+j][2*c2]  =u2lo(acc2[j]);
        outc[g*8+j][2*c2+1]=u2hi(acc2[j]);
    }
    __syncthreads();
    if(tid<64){
        float* row=outc[tid];
        float mbest=-1e30f; int jbest=9;
        for(int j=9;j<25;j++){ float v=row[j]; if(v>mbest){mbest=v; jbest=j;} }
        int primary=0;
        for(int p=0;p<9;p++) primary+=(row[p]>=mbest);
        float sec=(jbest<17)?0.f:((jbest<24)?1.f:-10.f);
        g_tot[b*512+w0+tid]=(float)primary+sec;
    }
}

// ---------- rank ----------
__global__ void rank_k(){
    int b=blockIdx.x, t=threadIdx.x; // 512
    __shared__ float tv[512];
    tv[t]=g_tot[b*512+t]; __syncthreads();
    float mv=tv[t]; int gt=0, lt=0, eqb=0;
    for(int j=0;j<512;j++){
        float o=tv[j];
        gt+=(o>mv); lt+=(o<mv); eqb+=((o==mv)&&(j<t));
    }
    int rmax=gt+eqb, rmin=lt+eqb;
    g_flags[b*512+t]=((rmax<256)?1:0)|((rmin<256)?2:0);
    if(rmax==0) g_search[b]=g_topidx[b*512+t];
}

// ---------- final pooled outputs ----------
__global__ void final_acc_k(const float* __restrict__ vocab){
    int b=blockIdx.y, c=blockIdx.x, t=threadIdx.x; // 256
    const int* ti=g_topidx+b*512+c*64;
    const int* fl=g_flags+b*512+c*64;
    float amax[3]={0,0,0}, amin[3]={0,0,0};
    for(int w=0;w<64;w++){
        int f=fl[w];
        if(f){
            const float* row=vocab+(size_t)ti[w]*768;
#pragma unroll
            for(int i=0;i<3;i++){
                float v=row[t+i*256];
                if(f&1) amax[i]+=v;
                if(f&2) amin[i]+=v;
            }
        }
    }
    float* pp=g_pp+(size_t)(b*8+c)*2*768;
#pragma unroll
    for(int i=0;i<3;i++){
        pp[t+i*256]=amax[i];
        pp[768+t+i*256]=amin[i];
    }
}
__global__ void final_red_k(const float* __restrict__ vocab, float* __restrict__ out){
    int b=blockIdx.x, t=threadIdx.x; // 256
    __shared__ float red[256];
    float amax[3]={0,0,0}, amin[3]={0,0,0};
    for(int c=0;c<8;c++){
        const float* pp=g_pp+(size_t)(b*8+c)*2*768;
#pragma unroll
        for(int i=0;i<3;i++){
            amax[i]+=pp[t+i*256];
            amin[i]+=pp[768+t+i*256];
        }
    }
    float loc=0.f;
#pragma unroll
    for(int i=0;i<3;i++){ amax[i]*=(1.f/256.f); loc+=amax[i]*amax[i]; }
    red[t]=loc; __syncthreads();
    for(int s=128;s>0;s>>=1){ if(t<s) red[t]+=red[t+s]; __syncthreads(); }
    float inv=1.f/fmaxf(sqrtf(red[0]),1e-12f);
#pragma unroll
    for(int i=0;i<3;i++) out[2*49152+b*768+t+i*256]=amax[i]*inv;
    __syncthreads();
    loc=0.f;
#pragma unroll
    for(int i=0;i<3;i++){ amin[i]*=(1.f/256.f); loc+=amin[i]*amin[i]; }
    red[t]=loc; __syncthreads();
    for(int s=128;s>0;s>>=1){ if(t<s) red[t]+=red[t+s]; __syncthreads(); }
    inv=1.f/fmaxf(sqrtf(red[0]),1e-12f);
#pragma unroll
    for(int i=0;i<3;i++) out[3*49152+b*768+t+i*256]=amin[i]*inv;
    int sw=g_search[b];
#pragma unroll
    for(int i=0;i<3;i++) out[49152+b*768+t+i*256]=vocab[(size_t)sw*768+t+i*256];
}

extern "C" void kernel_launch(void* const* d_in, const int* in_sizes, int n_in,
                              void* d_out, int out_size){
    const float* pos  =(const float*)d_in[0];
    const float* neg  =(const float*)d_in[1];
    const float* neut =(const float*)d_in[2];
    const float* assas=(const float*)d_in[3];
    const float* vocab=(const float*)d_in[4];
    const float* W1=(const float*)d_in[5];  const float* b1=(const float*)d_in[6];
    const float* W2=(const float*)d_in[7];  const float* b2=(const float*)d_in[8];
    const float* W3=(const float*)d_in[9];  const float* b3=(const float*)d_in[10];
    const float* W4=(const float*)d_in[11]; const float* b4=(const float*)d_in[12];
    float* out=(float*)d_out;

    float *gx, *gh1, *gh2, *gh3, *gh4, *gpart;
    cudaGetSymbolAddress((void**)&gx,   g_x);
    cudaGetSymbolAddress((void**)&gh1,  g_h1);
    cudaGetSymbolAddress((void**)&gh2,  g_h2);
    cudaGetSymbolAddress((void**)&gh3,  g_h3);
    cudaGetSymbolAddress((void**)&gh4,  g_h4);
    cudaGetSymbolAddress((void**)&gpart,g_part);

    prep_k<<<dim3(29,64),256>>>(pos,neg,neut,assas);

    // exact fp32 MLP (R12-base config)
    gemmT_k<<<dim3(18,24),256>>>(gx,W1,gpart,3072,2304,128);
    combine_act_k<<<(64*2304+255)/256,256>>>(gpart,b1,gh1,2304,24,1);
    gemmT_k<<<dim3(14,18),256>>>(gh1,W2,gpart,2304,1700,128);
    combine_act_k<<<(64*1700+255)/256,256>>>(gpart,b2,gh2,1700,18,1);
    gemmT_k<<<dim3(8,27),256>>>(gh2,W3,gpart,1700,1000,64);
    combine_act_k<<<(64*1000+255)/256,256>>>(gpart,b3,gh3,1000,27,1);
    gemmT_k<<<dim3(6,32),256>>>(gh3,W4,gpart,1000,768,32);
    combine_act_k<<<(64*768+255)/256,256>>>(gpart,b4,gh4,768,32,0);

    norm_mo_k<<<64,256>>>(out);
    bfrag_k<<<dim3(48,8),32>>>();
    sims_mma_k<<<(VOC+255)/256,256>>>(vocab);

    sel_k<<<64,1024>>>();
    collect_k<<<dim3(8,64),512>>>();
    final_sel_k<<<64,512>>>();

    combined_k<<<dim3(8,64),128>>>(vocab);
    rank_k<<<64,512>>>();
    final_acc_k<<<dim3(8,64),256>>>(vocab);
    final_red_k<<<64,256>>>(vocab,out);
}

// round 15
// speedup vs baseline: 1.1224x; 1.0790x over previous
#include <cuda_runtime.h>
#include <cuda_bf16.h>
#include <math.h>
#include <stdint.h>

#define Bsz 64
#define Dd  768
#define VOC 100000
#define KTOP 512

typedef unsigned long long u64t;

// ---------- scratch ----------
__device__ float g_x [Bsz*3072];
__device__ float g_h1[Bsz*2304];
__device__ float g_h2[Bsz*1700];
__device__ float g_h3[Bsz*1000];
__device__ float g_h4[Bsz*768];
__device__ float g_mo[Bsz*768];
__device__ uint2 g_bfh[48*8*32];               // hi bf16 B fragments [k16][nb][lane]
__device__ uint2 g_bfl[48*8*32];               // lo bf16 B fragments
__device__ float g_cluet[Bsz*768*32];          // cols 25..31 never written -> zero
__device__ float g_sims[(size_t)Bsz*VOC];
__device__ unsigned g_hist[Bsz*65536];         // zero-invariant across replays
__device__ int      g_thr[Bsz];
__device__ unsigned g_cnt[Bsz];
__device__ u64t     g_cand[Bsz*4096];
__device__ int   g_topidx[Bsz*KTOP];
__device__ float g_tot[Bsz*KTOP];
__device__ int   g_flags[Bsz*KTOP];
__device__ int   g_search[Bsz];
__device__ float g_part[3538944];
__device__ float g_pp[Bsz*8*2*768];

__device__ __forceinline__ unsigned f2u(float f){
    unsigned u = __float_as_uint(f);
    return (u & 0x80000000u) ? ~u : (u | 0x80000000u);
}
__device__ __forceinline__ u64t ffma2(u64t a, u64t b, u64t c){
    u64t d;
    asm("fma.rn.f32x2 %0, %1, %2, %3;" : "=l"(d) : "l"(a), "l"(b), "l"(c));
    return d;
}
__device__ __forceinline__ float u2lo(u64t v){ return __uint_as_float((unsigned)v); }
__device__ __forceinline__ float u2hi(u64t v){ return __uint_as_float((unsigned)(v>>32)); }

__device__ __forceinline__ void fsplit2(float2 f, unsigned &hi, unsigned &lo){
    unsigned h;
    asm("cvt.rn.bf16x2.f32 %0, %1, %2;" : "=r"(h) : "f"(f.y), "f"(f.x));
    float h0=__uint_as_float(h<<16);
    float h1=__uint_as_float(h&0xffff0000u);
    float l0=f.x-h0, l1=f.y-h1;
    asm("cvt.rn.bf16x2.f32 %0, %1, %2;" : "=r"(lo) : "f"(l1), "f"(l0));
    hi=h;
}

#define MMA_BF16(D,A0,A1,A2,A3,B0,B1) \
  asm volatile("mma.sync.aligned.m16n8k16.row.col.f32.bf16.bf16.f32 " \
    "{%0,%1,%2,%3},{%4,%5,%6,%7},{%8,%9},{%0,%1,%2,%3};" \
    : "+f"(D[0]),"+f"(D[1]),"+f"(D[2]),"+f"(D[3]) \
    : "r"(A0),"r"(A1),"r"(A2),"r"(A3),"r"(B0),"r"(B1))

#define CP16(dst,src) asm volatile("cp.async.cg.shared.global [%0], [%1], 16;" :: "r"(dst), "l"(src))
#define CPCOMMIT() asm volatile("cp.async.commit_group;" ::: "memory")

// ---------- stage 1 fused: pool-concat (g<4) + clue-norm (g>=4) ----------
__global__ void prep_k(const float* __restrict__ pos, const float* __restrict__ neg,
                       const float* __restrict__ neut, const float* __restrict__ assas){
    int b=blockIdx.y, g=blockIdx.x, t=threadIdx.x;
    __shared__ float red[256];
    if(g<4){
        const float* src; int n, xoff;
        if(g==0){src=neg +(size_t)b*8*Dd; n=8; xoff=0;}
        else if(g==1){src=assas+(size_t)b*Dd; n=1; xoff=Dd;}
        else if(g==2){src=neut+(size_t)b*7*Dd; n=7; xoff=2*Dd;}
        else {src=pos +(size_t)b*9*Dd; n=9; xoff=3*Dd;}
        float m[3];
#pragma unroll
        for(int i=0;i<3;i++){int d=t+i*256; float s=0.f;
            for(int j=0;j<n;j++) s+=src[(size_t)j*Dd+d]; m[i]=s/(float)n;}
        if(g==1){
#pragma unroll
            for(int i=0;i<3;i++) g_x[b*3072+xoff+t+i*256]=m[i];
            return;
        }
        red[t]=m[0]*m[0]+m[1]*m[1]+m[2]*m[2]; __syncthreads();
        for(int s=128;s>0;s>>=1){ if(t<s) red[t]+=red[t+s]; __syncthreads(); }
        float inv=1.f/fmaxf(sqrtf(red[0]),1e-12f);
#pragma unroll
        for(int i=0;i<3;i++) g_x[b*3072+xoff+t+i*256]=m[i]*inv;
    } else {
        int c=g-4;
        const float* src;
        if(c<9)       src=pos +((size_t)b*9+c)*Dd;
        else if(c<17) src=neg +((size_t)b*8+(c-9))*Dd;
        else if(c<24) src=neut+((size_t)b*7+(c-17))*Dd;
        else          src=assas+(size_t)b*Dd;
        float m[3]; float loc=0.f;
#pragma unroll
        for(int i=0;i<3;i++){ m[i]=src[t+i*256]; loc+=m[i]*m[i]; }
        red[t]=loc; __syncthreads();
        for(int s=128;s>0;s>>=1){ if(t<s) red[t]+=red[t+s]; __syncthreads(); }
        float inv=1.f/fmaxf(sqrtf(red[0]),1e-12f);
#pragma unroll
        for(int i=0;i<3;i++) g_cluet[((size_t)b*768+t+i*256)*32+c]=m[i]*inv;
    }
}

// ---------- MLP GEMM: exact fp32 FFMA2, 3-stage cp.async W streaming ----------
__global__ void __launch_bounds__(256) gemmT_k(const float* __restrict__ X, const float* __restrict__ W,
        float* __restrict__ part, int Kdim, int Ndim, int kchunk){
    __shared__ float ws[3][16][132];
    __shared__ float msd[2][16][132];
    int tid=threadIdx.x;
    int n0=blockIdx.x*128;
    int kbeg=blockIdx.y*kchunk, kend=min(Kdim,kbeg+kchunk);
    int niter=(kend-kbeg+15)>>4;
    int rg=tid&31, cg=tid>>5;
    u64t acc2[2][8];
#pragma unroll
    for(int i=0;i<2;i++)
#pragma unroll
        for(int j=0;j<8;j++) acc2[i][j]=0ull;

    int kr[2], c4w[2];
#pragma unroll
    for(int i=0;i<2;i++){ int q=tid+i*256; kr[i]=q>>5; c4w[i]=(q&31)*4; }
    unsigned wsb=(unsigned)__cvta_generic_to_shared(&ws[0][0][0]);

    // W stage issue: stage buffer = it%3, rows kbeg+16*it+kr
#define ISSUE_W(it) do{ \
        int sb=(it)%3; \
        _Pragma("unroll") \
        for(int i=0;i<2;i++){ \
            int k=kbeg+(it)*16+kr[i]; \
            int n=n0+c4w[i]; \
            if(k<kend && n+3<Ndim){ \
                CP16(wsb+(unsigned)(((sb*16+kr[i])*132+c4w[i])*4), W+(size_t)k*Ndim+n); \
            } else { \
                float4 v=make_float4(0,0,0,0); \
                if(k<kend){ \
                    if(n<Ndim)   v.x=W[(size_t)k*Ndim+n]; \
                    if(n+1<Ndim) v.y=W[(size_t)k*Ndim+n+1]; \
                    if(n+2<Ndim) v.z=W[(size_t)k*Ndim+n+2]; \
                    if(n+3<Ndim) v.w=W[(size_t)k*Ndim+n+3]; \
                } \
                *(float4*)&ws[sb][kr[i]][c4w[i]]=v; \
            } \
        } \
        CPCOMMIT(); \
    }while(0)

    ISSUE_W(0);
    if(niter>1) ISSUE_W(1);

    float4 xr;
    {
        int r=tid>>2, c4=(tid&3)*4;
        int k=kbeg+c4;
        xr=make_float4(0,0,0,0);
        if(k<kend) xr=*(const float4*)(X+(size_t)r*Kdim+k);
    }

    for(int it=0;it<niter;it++){
        {   // msd store from xr
            int r=tid>>2, c4=(tid&3)*4;
            float vv[4]={xr.x,xr.y,xr.z,xr.w};
#pragma unroll
            for(int j=0;j<4;j++)
                *(float2*)&msd[it&1][c4+j][2*r]=make_float2(vv[j],vv[j]);
        }
        if(it+1<niter){   // prefetch X for next iter
            int r=tid>>2, c4=(tid&3)*4;
            int k=kbeg+(it+1)*16+c4;
            xr=make_float4(0,0,0,0);
            if(k<kend) xr=*(const float4*)(X+(size_t)r*Kdim+k);
        }
        if(it<niter-1) asm volatile("cp.async.wait_group 1;" ::: "memory");
        else           asm volatile("cp.async.wait_group 0;" ::: "memory");
        __syncthreads();
        if(it+2<niter) ISSUE_W(it+2);
        const float (*wsc)[132]=ws[it%3];
        const float (*msc)[132]=msd[it&1];
#pragma unroll
        for(int kk=0;kk<16;kk++){
            const u64t* ap=(const u64t*)&wsc[kk][rg*4];
            u64t a0=ap[0], a1=ap[1];
            const u64t* bp=(const u64t*)&msc[kk][cg*16];
#pragma unroll
            for(int j=0;j<8;j++){
                u64t bv=bp[j];
                acc2[0][j]=ffma2(a0,bv,acc2[0][j]);
                acc2[1][j]=ffma2(a1,bv,acc2[1][j]);
            }
        }
        __syncthreads();
    }
    float* dst=part+(size_t)blockIdx.y*Bsz*Ndim;
#pragma unroll
    for(int i=0;i<2;i++){
        int n=n0+rg*4+2*i;
#pragma unroll
        for(int j=0;j<8;j++){
            int row=cg*8+j;
            if(n<Ndim)   dst[(size_t)row*Ndim+n]  =u2lo(acc2[i][j]);
            if(n+1<Ndim) dst[(size_t)row*Ndim+n+1]=u2hi(acc2[i][j]);
        }
    }
}

__global__ void combine_act_k(const float* __restrict__ part, const float* __restrict__ bias,
                              float* __restrict__ Y, int Ndim, int S, int act){
    int idx=blockIdx.x*blockDim.x+threadIdx.x;
    int total=Bsz*Ndim;
    if(idx>=total) return;
    int c=idx%Ndim;
    float s=bias[c];
    for(int sp=0;sp<S;sp++) s+=part[(size_t)sp*total+idx];
    Y[idx]=act?tanhf(s):s;
}

__global__ void norm_mo_k(float* __restrict__ out){
    int b=blockIdx.x, t=threadIdx.x;
    __shared__ float red[256];
    float m[3]; float loc=0.f;
#pragma unroll
    for(int i=0;i<3;i++){ m[i]=g_h4[b*768+t+i*256]; loc+=m[i]*m[i]; }
    red[t]=loc; __syncthreads();
    for(int s=128;s>0;s>>=1){ if(t<s) red[t]+=red[t+s]; __syncthreads(); }
    float inv=1.f/fmaxf(sqrtf(red[0]),1e-12f);
#pragma unroll
    for(int i=0;i<3;i++){
        float v=m[i]*inv;
        int k=t+i*256;
        g_mo[b*768+k]=v;
        out[b*768+k]=v;
    }
}

// ---------- B fragments: model_out split to bf16 hi/lo, [k16][nb][lane] ----------
__global__ void bfrag_k(){
    int k16=blockIdx.x, nb=blockIdx.y, lane=threadIdx.x;
    int g=lane>>2, tq=lane&3;
    int n=nb*8+g;
    int k0=k16*16+tq*2;
    const float* B=g_mo+(size_t)n*768;
    float2 v0=make_float2(B[k0],B[k0+1]);
    float2 v1=make_float2(B[k0+8],B[k0+9]);
    unsigned h0,l0,h1,l1;
    fsplit2(v0,h0,l0); fsplit2(v1,h1,l1);
    g_bfh[(k16*8+nb)*32+lane]=make_uint2(h0,h1);
    g_bfl[(k16*8+nb)*32+lane]=make_uint2(l0,l1);
}

// ---------- sims: split-bf16 mma, cp.async smem double-buffered vocab (R12-base) ----------
#define RSTR 20
__global__ void __launch_bounds__(256) sims_mma_k(const float* __restrict__ vocab){
    __shared__ float sbuf[2][256*RSTR];
    int tid=threadIdx.x, w=tid>>5, lane=tid&31;
    int g=lane>>2, tq=lane&3;
    int base=blockIdx.x*256 + w*32;
    int r[4]={base+g, base+8+g, base+16+g, base+24+g};
    bool ok[4];
#pragma unroll
    for(int i=0;i<4;i++) ok[i]=r[i]<VOC;

    const float* src[4];
    unsigned doff[4];
#pragma unroll
    for(int i=0;i<4;i++){
        int q=i*256+tid;
        int rowl=q>>2, seg=q&3;
        int rowg=blockIdx.x*256+rowl; if(rowg>=VOC) rowg=VOC-1;
        src[i]=vocab+(size_t)rowg*768+seg*4;
        doff[i]=(unsigned)((rowl*RSTR+seg*4)*4);
    }
    unsigned sb0=(unsigned)__cvta_generic_to_shared(&sbuf[0][0]);
    unsigned sb1=(unsigned)__cvta_generic_to_shared(&sbuf[1][0]);

#pragma unroll
    for(int i=0;i<4;i++) CP16(sb0+doff[i], src[i]);
    CPCOMMIT();

    float d[2][8][4];
#pragma unroll
    for(int t=0;t<2;t++)
#pragma unroll
        for(int i=0;i<8;i++)
#pragma unroll
            for(int j=0;j<4;j++) d[t][i][j]=0.f;
    float sq[4]={0,0,0,0};

    int rl[4];
#pragma unroll
    for(int i=0;i<4;i++) rl[i]=w*32+i*8+g;

    for(int k16=0;k16<48;k16++){
        unsigned sbn=(k16&1)?sb0:sb1;
        if(k16<47){
#pragma unroll
            for(int i=0;i<4;i++) CP16(sbn+doff[i], src[i]+(k16+1)*16);
            CPCOMMIT();
            asm volatile("cp.async.wait_group 1;" ::: "memory");
        } else {
            asm volatile("cp.async.wait_group 0;" ::: "memory");
        }
        __syncthreads();
        const float* bp=(k16&1)?sbuf[1]:sbuf[0];
        float2 f[4][2];
#pragma unroll
        for(int i=0;i<4;i++){
            f[i][0]=*(const float2*)(bp+rl[i]*RSTR+tq*2);
            f[i][1]=*(const float2*)(bp+rl[i]*RSTR+tq*2+8);
            sq[i]+=f[i][0].x*f[i][0].x+f[i][0].y*f[i][0].y
                  +f[i][1].x*f[i][1].x+f[i][1].y*f[i][1].y;
        }
        unsigned ah[4][2], al[4][2];
#pragma unroll
        for(int i=0;i<4;i++){
            fsplit2(f[i][0],ah[i][0],al[i][0]);
            fsplit2(f[i][1],ah[i][1],al[i][1]);
        }
        const uint2* bhp=g_bfh+(size_t)k16*256+lane;
        const uint2* blp=g_bfl+(size_t)k16*256+lane;
#pragma unroll
        for(int nb=0;nb<8;nb++){
            uint2 bh=bhp[nb*32];
            uint2 bl=blp[nb*32];
            MMA_BF16(d[0][nb],ah[0][0],ah[1][0],ah[0][1],ah[1][1],bh.x,bh.y);
            MMA_BF16(d[0][nb],al[0][0],al[1][0],al[0][1],al[1][1],bh.x,bh.y);
            MMA_BF16(d[0][nb],ah[0][0],ah[1][0],ah[0][1],ah[1][1],bl.x,bl.y);
            MMA_BF16(d[1][nb],ah[2][0],ah[3][0],ah[2][1],ah[3][1],bh.x,bh.y);
            MMA_BF16(d[1][nb],al[2][0],al[3][0],al[2][1],al[3][1],bh.x,bh.y);
            MMA_BF16(d[1][nb],ah[2][0],ah[3][0],ah[2][1],ah[3][1],bl.x,bl.y);
        }
        __syncthreads();
    }
    float ri[4];
#pragma unroll
    for(int i=0;i<4;i++){
        sq[i]+=__shfl_xor_sync(0xffffffff,sq[i],1);
        sq[i]+=__shfl_xor_sync(0xffffffff,sq[i],2);
        ri[i]=1.f/fmaxf(sqrtf(sq[i]),1e-12f);
    }
#pragma unroll
    for(int t=0;t<2;t++){
#pragma unroll
        for(int nb=0;nb<8;nb++){
            int n0=nb*8+tq*2;
            if(ok[2*t]){
                float s0=d[t][nb][0]*ri[2*t], s1=d[t][nb][1]*ri[2*t];
                g_sims[(size_t)n0*VOC+r[2*t]]=s0;
                g_sims[(size_t)(n0+1)*VOC+r[2*t]]=s1;
                atomicAdd(&g_hist[(size_t)n0*65536+(f2u(s0)>>16)],1u);
                atomicAdd(&g_hist[(size_t)(n0+1)*65536+(f2u(s1)>>16)],1u);
            }
            if(ok[2*t+1]){
                float s2=d[t][nb][2]*ri[2*t+1], s3=d[t][nb][3]*ri[2*t+1];
                g_sims[(size_t)n0*VOC+r[2*t+1]]=s2;
                g_sims[(size_t)(n0+1)*VOC+r[2*t+1]]=s3;
                atomicAdd(&g_hist[(size_t)n0*65536+(f2u(s2)>>16)],1u);
                atomicAdd(&g_hist[(size_t)(n0+1)*65536+(f2u(s3)>>16)],1u);
            }
        }
    }
}

// ---------- top-512 ----------
__global__ void sel_k(){
    int b=blockIdx.x, t=threadIdx.x;  // 1024
    __shared__ unsigned ssum[1024];
    unsigned* h=g_hist+(size_t)b*65536;
    int base=t*64;
    unsigned s=0;
    for(int i=0;i<64;i++) s+=h[base+i];
    ssum[t]=s; __syncthreads();
    unsigned above=0;
    for(int j=t+1;j<1024;j++) above+=ssum[j];
    if(above<512u && above+s>=512u){
        unsigned run=above;
        for(int i=63;i>=0;i--){
            unsigned hv=h[base+i];
            if(run+hv>=512u){ g_thr[b]=base+i; break; }
            run+=hv;
        }
    }
    __syncthreads();
#pragma unroll
    for(int i=0;i<64;i++) h[i*1024+t]=0u;   // coalesced re-zero (zero-invariant)
    if(t==0) g_cnt[b]=0u;
}
__global__ void collect_k(){
    int b=blockIdx.y, t=threadIdx.x;
    int start=blockIdx.x*12500, end=start+12500;
    unsigned binb=(unsigned)g_thr[b];
    const float* srow=g_sims+(size_t)b*VOC;
    for(int v=start+t;v<end;v+=512){
        unsigned u=f2u(srow[v]);
        if((u>>16)>=binb){
            unsigned pos=atomicAdd(&g_cnt[b],1u);
            if(pos<4096u) g_cand[(size_t)b*4096+pos]=((u64t)(~u)<<32)|(unsigned)v;
        }
    }
}
__global__ void final_sel_k(){
    int b=blockIdx.x, t=threadIdx.x;  // 512
    __shared__ u64t cand[4096];
    __shared__ u64t outk[512];
    int m=min(g_cnt[b],4096u);
    for(int i=t;i<m;i+=512) cand[i]=g_cand[(size_t)b*4096+i];
    __syncthreads();
    for(int i=t;i<m;i+=512){
        u64t key=cand[i]; int rank=0;
        for(int j=0;j<m;j++) rank+=(cand[j]<key);
        if(rank<512) outk[rank]=key;
    }
    __syncthreads();
    g_topidx[b*512+t]=(int)(outk[t]&0xffffffffu);
}

// ---------- gathered clue GEMM (FFMA2) + primary/secondary ----------
__global__ void __launch_bounds__(128) combined_k(const float* __restrict__ vocab){
    __shared__ float wsd[16][132];
    __shared__ float cs[16][32];
    __shared__ int sidx[64];
    __shared__ float outc[64][32];
    int b=blockIdx.y, w0=blockIdx.x*64, tid=threadIdx.x; // 128
    if(tid<64) sidx[tid]=g_topidx[b*512+w0+tid];
    __syncthreads();
    int c2=tid&15, g=tid>>4;
    u64t acc2[8];
#pragma unroll
    for(int i=0;i<8;i++) acc2[i]=0ull;
    for(int k0=0;k0<768;k0+=16){
#pragma unroll
        for(int i=0;i<2;i++){
            int q=tid+i*128, r=q>>2, c4=(q&3)*4;
            float4 v=*(const float4*)(vocab+(size_t)sidx[r]*768+k0+c4);
            float vv[4]={v.x,v.y,v.z,v.w};
#pragma unroll
            for(int j=0;j<4;j++)
                *(float2*)&wsd[c4+j][2*r]=make_float2(vv[j],vv[j]);
        }
        {
            int kk=tid>>3, cc4=(tid&7)*4;
            *(float4*)&cs[kk][cc4]=*(const float4*)(g_cluet+((size_t)b*768+k0+kk)*32+cc4);
        }
        __syncthreads();
#pragma unroll
        for(int kk=0;kk<16;kk++){
            u64t cv=*(const u64t*)&cs[kk][c2*2];
            const u64t* bp=(const u64t*)&wsd[kk][g*16];
#pragma unroll
            for(int j=0;j<8;j++)
                acc2[j]=ffma2(bp[j],cv,acc2[j]);
        }
        __syncthreads();
    }
#pragma unroll
    for(int j=0;j<8;j++){
        outc[g*8+j][2*c2]  =u2lo(acc2[j]);
        outc[g*8+j][2*c2+1]=u2hi(acc2[j]);
    }
    __syncthreads();
    if(tid<64){
        float* row=outc[tid];
        float mbest=-1e30f; int jbest=9;
        for(int j=9;j<25;j++){ float v=row[j]; if(v>mbest){mbest=v; jbest=j;} }
        int primary=0;
        for(int p=0;p<9;p++) primary+=(row[p]>=mbest);
        float sec=(jbest<17)?0.f:((jbest<24)?1.f:-10.f);
        g_tot[b*512+w0+tid]=(float)primary+sec;
    }
}

// ---------- rank ----------
__global__ void rank_k(){
    int b=blockIdx.x, t=threadIdx.x; // 512
    __shared__ float tv[512];
    tv[t]=g_tot[b*512+t]; __syncthreads();
    float mv=tv[t]; int gt=0, lt=0, eqb=0;
    for(int j=0;j<512;j++){
        float o=tv[j];
        gt+=(o>mv); lt+=(o<mv); eqb+=((o==mv)&&(j<t));
    }
    int rmax=gt+eqb, rmin=lt+eqb;
    g_flags[b*512+t]=((rmax<256)?1:0)|((rmin<256)?2:0);
    if(rmax==0) g_search[b]=g_topidx[b*512+t];
}

// ---------- final pooled outputs ----------
__global__ void final_acc_k(const float* __restrict__ vocab){
    int b=blockIdx.y, c=blockIdx.x, t=threadIdx.x; // 256
    const int* ti=g_topidx+b*512+c*64;
    const int* fl=g_flags+b*512+c*64;
    float amax[3]={0,0,0}, amin[3]={0,0,0};
    for(int w=0;w<64;w++){
        int f=fl[w];
        if(f){
            const float* row=vocab+(size_t)ti[w]*768;
#pragma unroll
            for(int i=0;i<3;i++){
                float v=row[t+i*256];
                if(f&1) amax[i]+=v;
                if(f&2) amin[i]+=v;
            }
        }
    }
    float* pp=g_pp+(size_t)(b*8+c)*2*768;
#pragma unroll
    for(int i=0;i<3;i++){
        pp[t+i*256]=amax[i];
        pp[768+t+i*256]=amin[i];
    }
}
__global__ void final_red_k(const float* __restrict__ vocab, float* __restrict__ out){
    int b=blockIdx.x, t=threadIdx.x; // 256
    __shared__ float red[256];
    float amax[3]={0,0,0}, amin[3]={0,0,0};
    for(int c=0;c<8;c++){
        const float* pp=g_pp+(size_t)(b*8+c)*2*768;
#pragma unroll
        for(int i=0;i<3;i++){
            amax[i]+=pp[t+i*256];
            amin[i]+=pp[768+t+i*256];
        }
    }
    float loc=0.f;
#pragma unroll
    for(int i=0;i<3;i++){ amax[i]*=(1.f/256.f); loc+=amax[i]*amax[i]; }
    red[t]=loc; __syncthreads();
    for(int s=128;s>0;s>>=1){ if(t<s) red[t]+=red[t+s]; __syncthreads(); }
    float inv=1.f/fmaxf(sqrtf(red[0]),1e-12f);
#pragma unroll
    for(int i=0;i<3;i++) out[2*49152+b*768+t+i*256]=amax[i]*inv;
    __syncthreads();
    loc=0.f;
#pragma unroll
    for(int i=0;i<3;i++){ amin[i]*=(1.f/256.f); loc+=amin[i]*amin[i]; }
    red[t]=loc; __syncthreads();
    for(int s=128;s>0;s>>=1){ if(t<s) red[t]+=red[t+s]; __syncthreads(); }
    inv=1.f/fmaxf(sqrtf(red[0]),1e-12f);
#pragma unroll
    for(int i=0;i<3;i++) out[3*49152+b*768+t+i*256]=amin[i]*inv;
    int sw=g_search[b];
#pragma unroll
    for(int i=0;i<3;i++) out[49152+b*768+t+i*256]=vocab[(size_t)sw*768+t+i*256];
}

extern "C" void kernel_launch(void* const* d_in, const int* in_sizes, int n_in,
                              void* d_out, int out_size){
    const float* pos  =(const float*)d_in[0];
    const float* neg  =(const float*)d_in[1];
    const float* neut =(const float*)d_in[2];
    const float* assas=(const float*)d_in[3];
    const float* vocab=(const float*)d_in[4];
    const float* W1=(const float*)d_in[5];  const float* b1=(const float*)d_in[6];
    const float* W2=(const float*)d_in[7];  const float* b2=(const float*)d_in[8];
    const float* W3=(const float*)d_in[9];  const float* b3=(const float*)d_in[10];
    const float* W4=(const float*)d_in[11]; const float* b4=(const float*)d_in[12];
    float* out=(float*)d_out;

    float *gx, *gh1, *gh2, *gh3, *gh4, *gpart;
    cudaGetSymbolAddress((void**)&gx,   g_x);
    cudaGetSymbolAddress((void**)&gh1,  g_h1);
    cudaGetSymbolAddress((void**)&gh2,  g_h2);
    cudaGetSymbolAddress((void**)&gh3,  g_h3);
    cudaGetSymbolAddress((void**)&gh4,  g_h4);
    cudaGetSymbolAddress((void**)&gpart,g_part);

    prep_k<<<dim3(29,64),256>>>(pos,neg,neut,assas);

    // exact fp32 MLP (cp.async W pipeline)
    gemmT_k<<<dim3(18,24),256>>>(gx,W1,gpart,3072,2304,128);
    combine_act_k<<<(64*2304+255)/256,256>>>(gpart,b1,gh1,2304,24,1);
    gemmT_k<<<dim3(14,18),256>>>(gh1,W2,gpart,2304,1700,128);
    combine_act_k<<<(64*1700+255)/256,256>>>(gpart,b2,gh2,1700,18,1);
    gemmT_k<<<dim3(8,27),256>>>(gh2,W3,gpart,1700,1000,64);
    combine_act_k<<<(64*1000+255)/256,256>>>(gpart,b3,gh3,1000,27,1);
    gemmT_k<<<dim3(6,32),256>>>(gh3,W4,gpart,1000,768,32);
    combine_act_k<<<(64*768+255)/256,256>>>(gpart,b4,gh4,768,32,0);

    norm_mo_k<<<64,256>>>(out);
    bfrag_k<<<dim3(48,8),32>>>();
    sims_mma_k<<<(VOC+255)/256,256>>>(vocab);

    sel_k<<<64,1024>>>();
    collect_k<<<dim3(8,64),512>>>();
    final_sel_k<<<64,512>>>();

    combined_k<<<dim3(8,64),128>>>(vocab);
    rank_k<<<64,512>>>();
    final_acc_k<<<dim3(8,64),256>>>(vocab);
    final_red_k<<<64,256>>>(vocab,out);
}

// round 16
// speedup vs baseline: 1.1568x; 1.0306x over previous
#include <cuda_runtime.h>
#include <cuda_bf16.h>
#include <math.h>
#include <stdint.h>

#define Bsz 64
#define Dd  768
#define VOC 100000
#define KTOP 512

typedef unsigned long long u64t;

// ---------- scratch ----------
__device__ float g_x [Bsz*3072];
__device__ float g_h1[Bsz*2304];
__device__ float g_h2[Bsz*1700];
__device__ float g_h3[Bsz*1000];
__device__ float g_h4[Bsz*768];
__device__ float g_mo[Bsz*768];
__device__ uint2 g_bfh[48*8*32];
__device__ uint2 g_bfl[48*8*32];
__device__ float g_cluet[Bsz*768*32];
__device__ float g_sims[(size_t)Bsz*VOC];
__device__ unsigned g_hist[Bsz*65536];         // zero-invariant across replays
__device__ int      g_thr[Bsz];
__device__ unsigned g_cnt[Bsz];
__device__ u64t     g_cand[Bsz*4096];
__device__ int   g_topidx[Bsz*KTOP];
__device__ float g_tot[Bsz*KTOP];
__device__ int   g_flags[Bsz*KTOP];
__device__ int   g_search[Bsz];
__device__ float g_part[3538944];
__device__ float g_pp[Bsz*8*2*768];

__device__ __forceinline__ unsigned f2u(float f){
    unsigned u = __float_as_uint(f);
    return (u & 0x80000000u) ? ~u : (u | 0x80000000u);
}
__device__ __forceinline__ u64t ffma2(u64t a, u64t b, u64t c){
    u64t d;
    asm("fma.rn.f32x2 %0, %1, %2, %3;" : "=l"(d) : "l"(a), "l"(b), "l"(c));
    return d;
}
__device__ __forceinline__ float u2lo(u64t v){ return __uint_as_float((unsigned)v); }
__device__ __forceinline__ float u2hi(u64t v){ return __uint_as_float((unsigned)(v>>32)); }

__device__ __forceinline__ void fsplit2(float2 f, unsigned &hi, unsigned &lo){
    unsigned h;
    asm("cvt.rn.bf16x2.f32 %0, %1, %2;" : "=r"(h) : "f"(f.y), "f"(f.x));
    float h0=__uint_as_float(h<<16);
    float h1=__uint_as_float(h&0xffff0000u);
    float l0=f.x-h0, l1=f.y-h1;
    asm("cvt.rn.bf16x2.f32 %0, %1, %2;" : "=r"(lo) : "f"(l1), "f"(l0));
    hi=h;
}

#define MMA_BF16(D,A0,A1,A2,A3,B0,B1) \
  asm volatile("mma.sync.aligned.m16n8k16.row.col.f32.bf16.bf16.f32 " \
    "{%0,%1,%2,%3},{%4,%5,%6,%7},{%8,%9},{%0,%1,%2,%3};" \
    : "+f"(D[0]),"+f"(D[1]),"+f"(D[2]),"+f"(D[3]) \
    : "r"(A0),"r"(A1),"r"(A2),"r"(A3),"r"(B0),"r"(B1))

#define CP16(dst,src) asm volatile("cp.async.cg.shared.global [%0], [%1], 16;" :: "r"(dst), "l"(src))
#define CPCOMMIT() asm volatile("cp.async.commit_group;" ::: "memory")

// ---------- stage 1 fused ----------
__global__ void prep_k(const float* __restrict__ pos, const float* __restrict__ neg,
                       const float* __restrict__ neut, const float* __restrict__ assas){
    int b=blockIdx.y, g=blockIdx.x, t=threadIdx.x;
    __shared__ float red[256];
    if(g<4){
        const float* src; int n, xoff;
        if(g==0){src=neg +(size_t)b*8*Dd; n=8; xoff=0;}
        else if(g==1){src=assas+(size_t)b*Dd; n=1; xoff=Dd;}
        else if(g==2){src=neut+(size_t)b*7*Dd; n=7; xoff=2*Dd;}
        else {src=pos +(size_t)b*9*Dd; n=9; xoff=3*Dd;}
        float m[3];
#pragma unroll
        for(int i=0;i<3;i++){int d=t+i*256; float s=0.f;
            for(int j=0;j<n;j++) s+=src[(size_t)j*Dd+d]; m[i]=s/(float)n;}
        if(g==1){
#pragma unroll
            for(int i=0;i<3;i++) g_x[b*3072+xoff+t+i*256]=m[i];
            return;
        }
        red[t]=m[0]*m[0]+m[1]*m[1]+m[2]*m[2]; __syncthreads();
        for(int s=128;s>0;s>>=1){ if(t<s) red[t]+=red[t+s]; __syncthreads(); }
        float inv=1.f/fmaxf(sqrtf(red[0]),1e-12f);
#pragma unroll
        for(int i=0;i<3;i++) g_x[b*3072+xoff+t+i*256]=m[i]*inv;
    } else {
        int c=g-4;
        const float* src;
        if(c<9)       src=pos +((size_t)b*9+c)*Dd;
        else if(c<17) src=neg +((size_t)b*8+(c-9))*Dd;
        else if(c<24) src=neut+((size_t)b*7+(c-17))*Dd;
        else          src=assas+(size_t)b*Dd;
        float m[3]; float loc=0.f;
#pragma unroll
        for(int i=0;i<3;i++){ m[i]=src[t+i*256]; loc+=m[i]*m[i]; }
        red[t]=loc; __syncthreads();
        for(int s=128;s>0;s>>=1){ if(t<s) red[t]+=red[t+s]; __syncthreads(); }
        float inv=1.f/fmaxf(sqrtf(red[0]),1e-12f);
#pragma unroll
        for(int i=0;i<3;i++) g_cluet[((size_t)b*768+t+i*256)*32+c]=m[i]*inv;
    }
}

// ---------- MLP GEMM: exact fp32 FFMA2 (R12-base) ----------
__global__ void __launch_bounds__(256) gemmT_k(const float* __restrict__ X, const float* __restrict__ W,
        float* __restrict__ part, int Kdim, int Ndim, int kchunk){
    __shared__ float ws[16][132];
    __shared__ float msd[16][132];
    int tid=threadIdx.x;
    int n0=blockIdx.x*128;
    int kbeg=blockIdx.y*kchunk, kend=min(Kdim,kbeg+kchunk);
    int rg=tid&31, cg=tid>>5;
    u64t acc2[2][8];
#pragma unroll
    for(int i=0;i<2;i++)
#pragma unroll
        for(int j=0;j<8;j++) acc2[i][j]=0ull;

    float4 wr[2], xr;
#pragma unroll
    for(int i=0;i<2;i++){
        int q=tid+i*256; int kr=q>>5, c4=(q&31)*4;
        int k=kbeg+kr, n=n0+c4;
        float4 v=make_float4(0,0,0,0);
        if(k<kend && n<Ndim) v=*(const float4*)(W+(size_t)k*Ndim+n);
        wr[i]=v;
    }
    {
        int r=tid>>2, c4=(tid&3)*4;
        int k=kbeg+c4;
        xr=make_float4(0,0,0,0);
        if(k<kend) xr=*(const float4*)(X+(size_t)r*Kdim+k);
    }
    for(int k0=kbeg;k0<kend;k0+=16){
#pragma unroll
        for(int i=0;i<2;i++){
            int q=tid+i*256; int kr=q>>5, c4=(q&31)*4;
            *(float4*)&ws[kr][c4]=wr[i];
        }
        {
            int r=tid>>2, c4=(tid&3)*4;
            float vv[4]={xr.x,xr.y,xr.z,xr.w};
#pragma unroll
            for(int j=0;j<4;j++)
                *(float2*)&msd[c4+j][2*r]=make_float2(vv[j],vv[j]);
        }
        __syncthreads();
        int kn=k0+16;
        if(kn<kend){
#pragma unroll
            for(int i=0;i<2;i++){
                int q=tid+i*256; int kr=q>>5, c4=(q&31)*4;
                int k=kn+kr, n=n0+c4;
                float4 v=make_float4(0,0,0,0);
                if(k<kend && n<Ndim) v=*(const float4*)(W+(size_t)k*Ndim+n);
                wr[i]=v;
            }
            {
                int r=tid>>2, c4=(tid&3)*4;
                int k=kn+c4;
                xr=make_float4(0,0,0,0);
                if(k<kend) xr=*(const float4*)(X+(size_t)r*Kdim+k);
            }
        }
#pragma unroll
        for(int kk=0;kk<16;kk++){
            const u64t* ap=(const u64t*)&ws[kk][rg*4];
            u64t a0=ap[0], a1=ap[1];
            const u64t* bp=(const u64t*)&msd[kk][cg*16];
#pragma unroll
            for(int j=0;j<8;j++){
                u64t bv=bp[j];
                acc2[0][j]=ffma2(a0,bv,acc2[0][j]);
                acc2[1][j]=ffma2(a1,bv,acc2[1][j]);
            }
        }
        __syncthreads();
    }
    float* dst=part+(size_t)blockIdx.y*Bsz*Ndim;
#pragma unroll
    for(int i=0;i<2;i++){
        int n=n0+rg*4+2*i;
#pragma unroll
        for(int j=0;j<8;j++){
            int row=cg*8+j;
            if(n<Ndim)   dst[(size_t)row*Ndim+n]  =u2lo(acc2[i][j]);
            if(n+1<Ndim) dst[(size_t)row*Ndim+n+1]=u2hi(acc2[i][j]);
        }
    }
}

__global__ void combine_act_k(const float* __restrict__ part, const float* __restrict__ bias,
                              float* __restrict__ Y, int Ndim, int S, int act){
    int idx=blockIdx.x*blockDim.x+threadIdx.x;
    int total=Bsz*Ndim;
    if(idx>=total) return;
    int c=idx%Ndim;
    float s=bias[c];
    for(int sp=0;sp<S;sp++) s+=part[(size_t)sp*total+idx];
    Y[idx]=act?tanhf(s):s;
}

__global__ void norm_mo_k(float* __restrict__ out){
    int b=blockIdx.x, t=threadIdx.x;
    __shared__ float red[256];
    float m[3]; float loc=0.f;
#pragma unroll
    for(int i=0;i<3;i++){ m[i]=g_h4[b*768+t+i*256]; loc+=m[i]*m[i]; }
    red[t]=loc; __syncthreads();
    for(int s=128;s>0;s>>=1){ if(t<s) red[t]+=red[t+s]; __syncthreads(); }
    float inv=1.f/fmaxf(sqrtf(red[0]),1e-12f);
#pragma unroll
    for(int i=0;i<3;i++){
        float v=m[i]*inv;
        int k=t+i*256;
        g_mo[b*768+k]=v;
        out[b*768+k]=v;
    }
}

// ---------- B fragments ----------
__global__ void bfrag_k(){
    int k16=blockIdx.x, nb=blockIdx.y, lane=threadIdx.x;
    int g=lane>>2, tq=lane&3;
    int n=nb*8+g;
    int k0=k16*16+tq*2;
    const float* B=g_mo+(size_t)n*768;
    float2 v0=make_float2(B[k0],B[k0+1]);
    float2 v1=make_float2(B[k0+8],B[k0+9]);
    unsigned h0,l0,h1,l1;
    fsplit2(v0,h0,l0); fsplit2(v1,h1,l1);
    g_bfh[(k16*8+nb)*32+lane]=make_uint2(h0,h1);
    g_bfl[(k16*8+nb)*32+lane]=make_uint2(l0,l1);
}

// ---------- sims (R12-base, twice-validated) ----------
#define RSTR 20
__global__ void __launch_bounds__(256) sims_mma_k(const float* __restrict__ vocab){
    __shared__ float sbuf[2][256*RSTR];
    int tid=threadIdx.x, w=tid>>5, lane=tid&31;
    int g=lane>>2, tq=lane&3;
    int base=blockIdx.x*256 + w*32;
    int r[4]={base+g, base+8+g, base+16+g, base+24+g};
    bool ok[4];
#pragma unroll
    for(int i=0;i<4;i++) ok[i]=r[i]<VOC;

    const float* src[4];
    unsigned doff[4];
#pragma unroll
    for(int i=0;i<4;i++){
        int q=i*256+tid;
        int rowl=q>>2, seg=q&3;
        int rowg=blockIdx.x*256+rowl; if(rowg>=VOC) rowg=VOC-1;
        src[i]=vocab+(size_t)rowg*768+seg*4;
        doff[i]=(unsigned)((rowl*RSTR+seg*4)*4);
    }
    unsigned sb0=(unsigned)__cvta_generic_to_shared(&sbuf[0][0]);
    unsigned sb1=(unsigned)__cvta_generic_to_shared(&sbuf[1][0]);

#pragma unroll
    for(int i=0;i<4;i++) CP16(sb0+doff[i], src[i]);
    CPCOMMIT();

    float d[2][8][4];
#pragma unroll
    for(int t=0;t<2;t++)
#pragma unroll
        for(int i=0;i<8;i++)
#pragma unroll
            for(int j=0;j<4;j++) d[t][i][j]=0.f;
    float sq[4]={0,0,0,0};

    int rl[4];
#pragma unroll
    for(int i=0;i<4;i++) rl[i]=w*32+i*8+g;

    for(int k16=0;k16<48;k16++){
        unsigned sbn=(k16&1)?sb0:sb1;
        if(k16<47){
#pragma unroll
            for(int i=0;i<4;i++) CP16(sbn+doff[i], src[i]+(k16+1)*16);
            CPCOMMIT();
            asm volatile("cp.async.wait_group 1;" ::: "memory");
        } else {
            asm volatile("cp.async.wait_group 0;" ::: "memory");
        }
        __syncthreads();
        const float* bp=(k16&1)?sbuf[1]:sbuf[0];
        float2 f[4][2];
#pragma unroll
        for(int i=0;i<4;i++){
            f[i][0]=*(const float2*)(bp+rl[i]*RSTR+tq*2);
            f[i][1]=*(const float2*)(bp+rl[i]*RSTR+tq*2+8);
            sq[i]+=f[i][0].x*f[i][0].x+f[i][0].y*f[i][0].y
                  +f[i][1].x*f[i][1].x+f[i][1].y*f[i][1].y;
        }
        unsigned ah[4][2], al[4][2];
#pragma unroll
        for(int i=0;i<4;i++){
            fsplit2(f[i][0],ah[i][0],al[i][0]);
            fsplit2(f[i][1],ah[i][1],al[i][1]);
        }
        const uint2* bhp=g_bfh+(size_t)k16*256+lane;
        const uint2* blp=g_bfl+(size_t)k16*256+lane;
#pragma unroll
        for(int nb=0;nb<8;nb++){
            uint2 bh=bhp[nb*32];
            uint2 bl=blp[nb*32];
            MMA_BF16(d[0][nb],ah[0][0],ah[1][0],ah[0][1],ah[1][1],bh.x,bh.y);
            MMA_BF16(d[0][nb],al[0][0],al[1][0],al[0][1],al[1][1],bh.x,bh.y);
            MMA_BF16(d[0][nb],ah[0][0],ah[1][0],ah[0][1],ah[1][1],bl.x,bl.y);
            MMA_BF16(d[1][nb],ah[2][0],ah[3][0],ah[2][1],ah[3][1],bh.x,bh.y);
            MMA_BF16(d[1][nb],al[2][0],al[3][0],al[2][1],al[3][1],bh.x,bh.y);
            MMA_BF16(d[1][nb],ah[2][0],ah[3][0],ah[2][1],ah[3][1],bl.x,bl.y);
        }
        __syncthreads();
    }
    float ri[4];
#pragma unroll
    for(int i=0;i<4;i++){
        sq[i]+=__shfl_xor_sync(0xffffffff,sq[i],1);
        sq[i]+=__shfl_xor_sync(0xffffffff,sq[i],2);
        ri[i]=1.f/fmaxf(sqrtf(sq[i]),1e-12f);
    }
#pragma unroll
    for(int t=0;t<2;t++){
#pragma unroll
        for(int nb=0;nb<8;nb++){
            int n0=nb*8+tq*2;
            if(ok[2*t]){
                float s0=d[t][nb][0]*ri[2*t], s1=d[t][nb][1]*ri[2*t];
                g_sims[(size_t)n0*VOC+r[2*t]]=s0;
                g_sims[(size_t)(n0+1)*VOC+r[2*t]]=s1;
                atomicAdd(&g_hist[(size_t)n0*65536+(f2u(s0)>>16)],1u);
                atomicAdd(&g_hist[(size_t)(n0+1)*65536+(f2u(s1)>>16)],1u);
            }
            if(ok[2*t+1]){
                float s2=d[t][nb][2]*ri[2*t+1], s3=d[t][nb][3]*ri[2*t+1];
                g_sims[(size_t)n0*VOC+r[2*t+1]]=s2;
                g_sims[(size_t)(n0+1)*VOC+r[2*t+1]]=s3;
                atomicAdd(&g_hist[(size_t)n0*65536+(f2u(s2)>>16)],1u);
                atomicAdd(&g_hist[(size_t)(n0+1)*65536+(f2u(s3)>>16)],1u);
            }
        }
    }
}

// ---------- top-512 ----------
__global__ void sel_k(){
    int b=blockIdx.x, t=threadIdx.x;  // 1024
    __shared__ unsigned ssum[1024];
    unsigned* h=g_hist+(size_t)b*65536;
    const uint4* h4=(const uint4*)(h+t*64);
    unsigned s=0;
#pragma unroll
    for(int i=0;i<16;i++){
        uint4 v=h4[i];
        s+=v.x+v.y+v.z+v.w;
    }
    ssum[t]=s; __syncthreads();
    unsigned above=0;
    for(int j=t+1;j<1024;j++) above+=ssum[j];
    if(above<512u && above+s>=512u){
        unsigned run=above;
        int base=t*64;
        for(int i=63;i>=0;i--){
            unsigned hv=h[base+i];
            if(run+hv>=512u){ g_thr[b]=base+i; break; }
            run+=hv;
        }
    }
    __syncthreads();
#pragma unroll
    for(int i=0;i<64;i++) h[i*1024+t]=0u;   // coalesced re-zero (zero-invariant)
    if(t==0) g_cnt[b]=0u;
}
__global__ void collect_k(){
    int b=blockIdx.y, t=threadIdx.x;
    int start=blockIdx.x*12500;
    unsigned binb=(unsigned)g_thr[b];
    const float* srow=g_sims+(size_t)b*VOC;
    // 12500 = 3125 float4 + 0 remainder? 12500/4=3125 exactly.
    const float4* s4=(const float4*)(srow+start);
    for(int q=t;q<3125;q+=512){
        float4 v=s4[q];
        int vbase=start+q*4;
        float vv[4]={v.x,v.y,v.z,v.w};
#pragma unroll
        for(int j=0;j<4;j++){
            unsigned u=f2u(vv[j]);
            if((u>>16)>=binb){
                unsigned pos=atomicAdd(&g_cnt[b],1u);
                if(pos<4096u) g_cand[(size_t)b*4096+pos]=((u64t)(~u)<<32)|(unsigned)(vbase+j);
            }
        }
    }
}
__global__ void final_sel_k(){
    int b=blockIdx.x, t=threadIdx.x;  // 512
    __shared__ u64t cand[4096];
    __shared__ u64t outk[512];
    int m=min(g_cnt[b],4096u);
    for(int i=t;i<m;i+=512) cand[i]=g_cand[(size_t)b*4096+i];
    __syncthreads();
    for(int i=t;i<m;i+=512){
        u64t key=cand[i]; int rank=0;
        for(int j=0;j<m;j++) rank+=(cand[j]<key);
        if(rank<512) outk[rank]=key;
    }
    __syncthreads();
    g_topidx[b*512+t]=(int)(outk[t]&0xffffffffu);
}

// ---------- gathered clue GEMM (FFMA2) + primary/secondary ----------
__global__ void __launch_bounds__(128) combined_k(const float* __restrict__ vocab){
    __shared__ float wsd[16][132];
    __shared__ float cs[16][32];
    __shared__ int sidx[64];
    __shared__ float outc[64][32];
    int b=blockIdx.y, w0=blockIdx.x*64, tid=threadIdx.x; // 128
    if(tid<64) sidx[tid]=g_topidx[b*512+w0+tid];
    __syncthreads();
    int c2=tid&15, g=tid>>4;
    u64t acc2[8];
#pragma unroll
    for(int i=0;i<8;i++) acc2[i]=0ull;
    for(int k0=0;k0<768;k0+=16){
#pragma unroll
        for(int i=0;i<2;i++){
            int q=tid+i*128, r=q>>2, c4=(q&3)*4;
            float4 v=*(const float4*)(vocab+(size_t)sidx[r]*768+k0+c4);
            float vv[4]={v.x,v.y,v.z,v.w};
#pragma unroll
            for(int j=0;j<4;j++)
                *(float2*)&wsd[c4+j][2*r]=make_float2(vv[j],vv[j]);
        }
        {
            int kk=tid>>3, cc4=(tid&7)*4;
            *(float4*)&cs[kk][cc4]=*(const float4*)(g_cluet+((size_t)b*768+k0+kk)*32+cc4);
        }
        __syncthreads();
#pragma unroll
        for(int kk=0;kk<16;kk++){
            u64t cv=*(const u64t*)&cs[kk][c2*2];
            const u64t* bp=(const u64t*)&wsd[kk][g*16];
#pragma unroll
            for(int j=0;j<8;j++)
                acc2[j]=ffma2(bp[j],cv,acc2[j]);
        }
        __syncthreads();
    }
#pragma unroll
    for(int j=0;j<8;j++){
        outc[g*8+j][2*c2]  =u2lo(acc2[j]);
        outc[g*8+j][2*c2+1]=u2hi(acc2[j]);
    }
    __syncthreads();
    if(tid<64){
        float* row=outc[tid];
        float mbest=-1e30f; int jbest=9;
        for(int j=9;j<25;j++){ float v=row[j]; if(v>mbest){mbest=v; jbest=j;} }
        int primary=0;
        for(int p=0;p<9;p++) primary+=(row[p]>=mbest);
        float sec=(jbest<17)?0.f:((jbest<24)?1.f:-10.f);
        g_tot[b*512+w0+tid]=(float)primary+sec;
    }
}

// ---------- rank ----------
__global__ void rank_k(){
    int b=blockIdx.x, t=threadIdx.x; // 512
    __shared__ float tv[512];
    tv[t]=g_tot[b*512+t]; __syncthreads();
    float mv=tv[t]; int gt=0, lt=0, eqb=0;
    for(int j=0;j<512;j++){
        float o=tv[j];
        gt+=(o>mv); lt+=(o<mv); eqb+=((o==mv)&&(j<t));
    }
    int rmax=gt+eqb, rmin=lt+eqb;
    g_flags[b*512+t]=((rmax<256)?1:0)|((rmin<256)?2:0);
    if(rmax==0) g_search[b]=g_topidx[b*512+t];
}

// ---------- final pooled outputs (float4 gather) ----------
__global__ void final_acc_k(const float* __restrict__ vocab){
    int b=blockIdx.y, c=blockIdx.x, t=threadIdx.x; // 192 threads, one float4 each
    const int* ti=g_topidx+b*512+c*64;
    const int* fl=g_flags+b*512+c*64;
    float4 amax=make_float4(0,0,0,0), amin=make_float4(0,0,0,0);
    for(int w=0;w<64;w++){
        int f=fl[w];
        if(f){
            float4 v=*(const float4*)(vocab+(size_t)ti[w]*768+t*4);
            if(f&1){ amax.x+=v.x; amax.y+=v.y; amax.z+=v.z; amax.w+=v.w; }
            if(f&2){ amin.x+=v.x; amin.y+=v.y; amin.z+=v.z; amin.w+=v.w; }
        }
    }
    float* pp=g_pp+(size_t)(b*8+c)*2*768;
    *(float4*)(pp+t*4)=amax;
    *(float4*)(pp+768+t*4)=amin;
}
__global__ void final_red_k(const float* __restrict__ vocab, float* __restrict__ out){
    int b=blockIdx.x, t=threadIdx.x; // 256
    __shared__ float red[256];
    float amax[3]={0,0,0}, amin[3]={0,0,0};
    for(int c=0;c<8;c++){
        const float* pp=g_pp+(size_t)(b*8+c)*2*768;
#pragma unroll
        for(int i=0;i<3;i++){
            amax[i]+=pp[t+i*256];
            amin[i]+=pp[768+t+i*256];
        }
    }
    float loc=0.f;
#pragma unroll
    for(int i=0;i<3;i++){ amax[i]*=(1.f/256.f); loc+=amax[i]*amax[i]; }
    red[t]=loc; __syncthreads();
    for(int s=128;s>0;s>>=1){ if(t<s) red[t]+=red[t+s]; __syncthreads(); }
    float inv=1.f/fmaxf(sqrtf(red[0]),1e-12f);
#pragma unroll
    for(int i=0;i<3;i++) out[2*49152+b*768+t+i*256]=amax[i]*inv;
    __syncthreads();
    loc=0.f;
#pragma unroll
    for(int i=0;i<3;i++){ amin[i]*=(1.f/256.f); loc+=amin[i]*amin[i]; }
    red[t]=loc; __syncthreads();
    for(int s=128;s>0;s>>=1){ if(t<s) red[t]+=red[t+s]; __syncthreads(); }
    inv=1.f/fmaxf(sqrtf(red[0]),1e-12f);
#pragma unroll
    for(int i=0;i<3;i++) out[3*49152+b*768+t+i*256]=amin[i]*inv;
    int sw=g_search[b];
#pragma unroll
    for(int i=0;i<3;i++) out[49152+b*768+t+i*256]=vocab[(size_t)sw*768+t+i*256];
}

extern "C" void kernel_launch(void* const* d_in, const int* in_sizes, int n_in,
                              void* d_out, int out_size){
    const float* pos  =(const float*)d_in[0];
    const float* neg  =(const float*)d_in[1];
    const float* neut =(const float*)d_in[2];
    const float* assas=(const float*)d_in[3];
    const float* vocab=(const float*)d_in[4];
    const float* W1=(const float*)d_in[5];  const float* b1=(const float*)d_in[6];
    const float* W2=(const float*)d_in[7];  const float* b2=(const float*)d_in[8];
    const float* W3=(const float*)d_in[9];  const float* b3=(const float*)d_in[10];
    const float* W4=(const float*)d_in[11]; const float* b4=(const float*)d_in[12];
    float* out=(float*)d_out;

    float *gx, *gh1, *gh2, *gh3, *gh4, *gpart;
    cudaGetSymbolAddress((void**)&gx,   g_x);
    cudaGetSymbolAddress((void**)&gh1,  g_h1);
    cudaGetSymbolAddress((void**)&gh2,  g_h2);
    cudaGetSymbolAddress((void**)&gh3,  g_h3);
    cudaGetSymbolAddress((void**)&gh4,  g_h4);
    cudaGetSymbolAddress((void**)&gpart,g_part);

    prep_k<<<dim3(29,64),256>>>(pos,neg,neut,assas);

    // exact fp32 MLP
    gemmT_k<<<dim3(18,24),256>>>(gx,W1,gpart,3072,2304,128);
    combine_act_k<<<(64*2304+255)/256,256>>>(gpart,b1,gh1,2304,24,1);
    gemmT_k<<<dim3(14,18),256>>>(gh1,W2,gpart,2304,1700,128);
    combine_act_k<<<(64*1700+255)/256,256>>>(gpart,b2,gh2,1700,18,1);
    gemmT_k<<<dim3(8,27),256>>>(gh2,W3,gpart,1700,1000,64);
    combine_act_k<<<(64*1000+255)/256,256>>>(gpart,b3,gh3,1000,27,1);
    gemmT_k<<<dim3(6,32),256>>>(gh3,W4,gpart,1000,768,32);
    combine_act_k<<<(64*768+255)/256,256>>>(gpart,b4,gh4,768,32,0);

    norm_mo_k<<<64,256>>>(out);
    bfrag_k<<<dim3(48,8),32>>>();
    sims_mma_k<<<(VOC+255)/256,256>>>(vocab);

    sel_k<<<64,1024>>>();
    collect_k<<<dim3(8,64),512>>>();
    final_sel_k<<<64,512>>>();

    combined_k<<<dim3(8,64),128>>>(vocab);
    rank_k<<<64,512>>>();
    final_acc_k<<<dim3(8,64),192>>>(vocab);
    final_red_k<<<64,256>>>(vocab,out);
}